// round 15
// baseline (speedup 1.0000x reference)
#include <cuda_runtime.h>
#include <cuda_fp16.h>
#include <stdint.h>
#include <math.h>

// Problem constants
#define H 256
#define H2 512
#define G 2048
#define E 262144
#define EPS 1e-5f
#define MT 128          // rows per tile (graph-side mma kernels)
#define MTE 64          // rows per tile (edge-side streamed kernels)
#define PA 264          // A-tile row stride (halves)
#define PW 264          // W-tile row stride (halves)
#define KCH 64          // K rows per streamed chunk
#define NCH 4           // chunks per 256-K matmul
#define NTH 512         // threads for graph-side mma kernels
#define NT_G (G / MT)   // 16 graph tiles

// ---------------- device scratch (16B aligned: vector access) ----------------
__device__ __align__(16) float  g_film[G * H];
__device__ __align__(16) __half g_xh[(size_t)E * H];   // MLP out (x)
__device__ __align__(16) float  g_selsum[G * H];
__device__ __align__(16) float  g_cnt[G];
__device__ __align__(16) float  g_Pc[G * H];
__device__ __align__(16) float  g_cs[G], g_csq[G];
__device__ __align__(16) float  g_vg[H], g_vb[H];
__device__ __align__(16) __half g_cg[G * H];           // cur * lh_g_lo
__device__ __align__(16) __half g_zn[G * H2];          // stop-head LN512 out
__device__ __align__(16) __half hQf[H * H];
__device__ __align__(16) __half hW0[H * H];
__device__ __align__(16) __half hW1[H * H];
__device__ __align__(16) __half hWh[H * H];
__device__ __align__(16) __half hPcW[H * H];
__device__ __align__(16) __half hSpW[H2 * H];
__device__ int g_maskmode;

// ---------------- helpers ----------------
__device__ __forceinline__ float gelu_f(float x) {
    return 0.5f * x * (1.0f + erff(x * 0.70710678118654752f));
}

__device__ __forceinline__ void warpReduce2(float &a, float &b) {
#pragma unroll
    for (int o = 16; o; o >>= 1) {
        a += __shfl_xor_sync(0xffffffffu, a, o);
        b += __shfl_xor_sync(0xffffffffu, b, o);
    }
}

// 256-thread block reduce (graphA only)
__device__ __forceinline__ void blockReduce2(float &a, float &b) {
    __shared__ float sa[8], sbx[8];
    int lane = threadIdx.x & 31, wid = threadIdx.x >> 5;
    warpReduce2(a, b);
    if (lane == 0) { sa[wid] = a; sbx[wid] = b; }
    __syncthreads();
    if (wid == 0) {
        a = (lane < 8) ? sa[lane] : 0.f;
        b = (lane < 8) ? sbx[lane] : 0.f;
#pragma unroll
        for (int o = 4; o; o >>= 1) {
            a += __shfl_xor_sync(0xffffffffu, a, o);
            b += __shfl_xor_sync(0xffffffffu, b, o);
        }
        if (lane == 0) { sa[0] = a; sbx[0] = b; }
    }
    __syncthreads();
    a = sa[0]; b = sbx[0];
    __syncthreads();
}

__device__ __forceinline__ float quad_reduce(float x) {
    x += __shfl_xor_sync(0xffffffffu, x, 1);
    x += __shfl_xor_sync(0xffffffffu, x, 2);
    return x;
}

__device__ __forceinline__ float mask_val(const void *p, int e, int mode) {
    if (mode == 0) return ((const int *)p)[e] != 0 ? 1.f : 0.f;
    if (mode == 1) return ((const float *)p)[e] != 0.f ? 1.f : 0.f;
    return ((const unsigned char *)p)[e] != 0 ? 1.f : 0.f;
}

__device__ __forceinline__ unsigned int s2u(const void *p) {
    return (unsigned int)__cvta_generic_to_shared(p);
}

__device__ __forceinline__ void ldm_x4(unsigned int &r0, unsigned int &r1,
                                       unsigned int &r2, unsigned int &r3,
                                       unsigned int addr) {
    asm volatile("ldmatrix.sync.aligned.m8n8.x4.shared.b16 {%0,%1,%2,%3}, [%4];"
                 : "=r"(r0), "=r"(r1), "=r"(r2), "=r"(r3) : "r"(addr));
}
__device__ __forceinline__ void ldm_x4_t(unsigned int &r0, unsigned int &r1,
                                         unsigned int &r2, unsigned int &r3,
                                         unsigned int addr) {
    asm volatile("ldmatrix.sync.aligned.m8n8.x4.trans.shared.b16 {%0,%1,%2,%3}, [%4];"
                 : "=r"(r0), "=r"(r1), "=r"(r2), "=r"(r3) : "r"(addr));
}
__device__ __forceinline__ void mma16816(float *c, unsigned int a0,
                                         unsigned int a1, unsigned int a2,
                                         unsigned int a3, unsigned int b0,
                                         unsigned int b1) {
    asm volatile(
        "mma.sync.aligned.m16n8k16.row.col.f32.f16.f16.f32 "
        "{%0,%1,%2,%3}, {%4,%5,%6,%7}, {%8,%9}, {%0,%1,%2,%3};"
        : "+f"(c[0]), "+f"(c[1]), "+f"(c[2]), "+f"(c[3])
        : "r"(a0), "r"(a1), "r"(a2), "r"(a3), "r"(b0), "r"(b1));
}

__device__ __forceinline__ void cp16(unsigned int saddr, const void *g) {
    asm volatile("cp.async.cg.shared.global [%0], [%1], 16;"
                 :: "r"(saddr), "l"(g) : "memory");
}
#define CP_COMMIT() asm volatile("cp.async.commit_group;" ::: "memory")
#define CP_WAIT0() asm volatile("cp.async.wait_group 0;" ::: "memory")

// ---- 16-warp graph-side mainloop: [128x256] @ [256x256], weights resident ----
__device__ __forceinline__ void mma_block(const __half *__restrict__ Ash,
                                          const __half *__restrict__ Wsh,
                                          float (&acc)[2][8][4], int lane,
                                          int wm, int wn) {
#pragma unroll 1
    for (int ks = 0; ks < 16; ks++) {
        unsigned int a[2][4];
#pragma unroll
        for (int mi = 0; mi < 2; mi++) {
            ldm_x4(a[mi][0], a[mi][1], a[mi][2], a[mi][3],
                   s2u(Ash + (32 * wm + 16 * mi + (lane & 15)) * PA + ks * 16 +
                       ((lane >> 4) << 3)));
        }
#pragma unroll
        for (int bi = 0; bi < 4; bi++) {
            unsigned int b0, b1, b2, b3;
            ldm_x4_t(b0, b1, b2, b3,
                     s2u(Wsh + (ks * 16 + (lane & 15)) * PW + 64 * wn + 16 * bi +
                         ((lane >> 4) << 3)));
#pragma unroll
            for (int mi = 0; mi < 2; mi++) {
                mma16816(acc[mi][2 * bi], a[mi][0], a[mi][1], a[mi][2], a[mi][3], b0, b1);
                mma16816(acc[mi][2 * bi + 1], a[mi][0], a[mi][1], a[mi][2], a[mi][3], b2, b3);
            }
        }
    }
}

// ---- edge-side chunk mainloop (KCH=64): 4 unrolled k-steps, hoisted bases ----
__device__ __forceinline__ void mma_chunk64(unsigned a0b, unsigned a1b,
                                            unsigned bb, float (&acc)[2][8][4],
                                            int kc) {
#pragma unroll
    for (int ks2 = 0; ks2 < 4; ks2++) {
        unsigned aoff = (unsigned)((kc * 4 + ks2) * 32);   // 16 halves = 32 B
        unsigned int a[2][4];
        ldm_x4(a[0][0], a[0][1], a[0][2], a[0][3], a0b + aoff);
        ldm_x4(a[1][0], a[1][1], a[1][2], a[1][3], a1b + aoff);
        unsigned bb2 = bb + (unsigned)(ks2 * (16 * PW * 2));
#pragma unroll
        for (int bi = 0; bi < 4; bi++) {
            unsigned int b0, b1, b2, b3;
            ldm_x4_t(b0, b1, b2, b3, bb2 + (unsigned)(bi * 32));
#pragma unroll
            for (int mi = 0; mi < 2; mi++) {
                mma16816(acc[mi][2 * bi], a[mi][0], a[mi][1], a[mi][2], a[mi][3], b0, b1);
                mma16816(acc[mi][2 * bi + 1], a[mi][0], a[mi][1], a[mi][2], a[mi][3], b2, b3);
            }
        }
    }
}

// prefetch one 64x256 weight chunk into smem via cp.async (2048 uint4, 256 thr)
__device__ __forceinline__ void prefetch_chunk(__half *Wc, const __half *Wg,
                                               int kc, int tid) {
    const __half *src = Wg + (size_t)kc * KCH * 256;
#pragma unroll
    for (int it = 0; it < 8; it++) {
        int idx = tid + 256 * it;       // 0..2047
        int row = idx >> 5, q = idx & 31;
        cp16(s2u(Wc + row * PW + q * 8), src + row * 256 + q * 8);
    }
    CP_COMMIT();
}

// load a 256x256 fp16 weight matrix into padded smem (8192 uint4, 512 threads)
__device__ __forceinline__ void load_weights(__half *Wsh, const __half *Wg, int tid) {
#pragma unroll
    for (int it = 0; it < 16; it++) {
        int idx = tid + NTH * it;
        int row = idx >> 5, q = idx & 31;
        *(uint4 *)(Wsh + row * PW + q * 8) = *(const uint4 *)(Wg + row * 256 + q * 8);
    }
}

extern __shared__ __align__(16) char dynsmem[];
#define WS_BYTES (256 * PW * 2)
#define DSMEM_G (WS_BYTES + MT * PA * 2)
#define DSMEM_E (MTE * PA * 2 + 2 * KCH * PW * 2)

// ---------------- K0: sniff + zero fused ----------------
__global__ void sniffzero_kernel(const void *mask) {
    if (blockIdx.x == 0) {
        const unsigned int *w = (const unsigned int *)mask;
        int i32ok = 1, f32ok = 1;
        for (int i = threadIdx.x; i < 4096; i += 256) {
            unsigned int x = w[i];
            if (x > 1u) i32ok = 0;
            float f = __uint_as_float(x);
            if (!(f == 0.f || f == 1.f)) f32ok = 0;
        }
        int all_i32 = __syncthreads_and(i32ok);
        int all_f32 = __syncthreads_and(f32ok);
        if (threadIdx.x == 0) g_maskmode = all_i32 ? 0 : (all_f32 ? 1 : 2);
    }
    int i = blockIdx.x * blockDim.x + threadIdx.x;
    if (i < G * H) g_selsum[i] = 0.f;
    if (i < G) g_cnt[i] = 0.f;
    if (i < H) { g_vg[i] = 0.f; g_vb[i] = 0.f; }
}

// ---------------- K2a: vg / vb (parallel atomic reduction, 16 blocks) ----------------
__global__ void prep_vg(const float *lh_g, const float *lh_b,
                        const float *lh_W1, const float *lh_b1) {
    int j = threadIdx.x;
    int k0 = blockIdx.x * 32;
    float a = 0.f, b = 0.f;
#pragma unroll
    for (int kk = 0; kk < 32; kk++) {
        int k = k0 + kk;
        float w = lh_W1[k * H + j];
        a += lh_g[k] * w;
        b += lh_b[k] * w;
    }
    atomicAdd(&g_vg[j], a);
    if (blockIdx.x == 0) b += lh_b1[j];
    atomicAdd(&g_vb[j], b);
}

// ---------------- K2b: fp16 weight conversion ----------------
__global__ void prep_half2(const float *qf_W, const float *mlp_W,
                           const float *lh_g, const float *lh_W1,
                           const float *sp_W1) {
    int i = blockIdx.x * 256 + threadIdx.x;
    int seg = i >> 16, off = i & 65535;
    switch (seg) {
        case 0: hQf[off] = __float2half(qf_W[off]); break;
        case 1: hW0[off] = __float2half(mlp_W[off]); break;
        case 2: hW1[off] = __float2half(mlp_W[65536 + off]); break;
        case 3: {
            int k = off >> 8;
            hWh[off] = __float2half(lh_g[H + k] * lh_W1[(H + k) * H + (off & 255)]);
        } break;
        case 4: hPcW[off] = __float2half(lh_W1[off]); break;
        case 5: hSpW[off] = __float2half(sp_W1[off]); break;
        case 6: hSpW[65536 + off] = __float2half(sp_W1[65536 + off]); break;
    }
}

// ---------------- film: g_film = gelu(LN(question)@qf_W + qf_bias) ----------------
__global__ __launch_bounds__(NTH, 1) void film_mma(const float *question,
                                                   const float *qf_g,
                                                   const float *qf_b,
                                                   const float *qf_bias) {
    __half *Wsh = (__half *)dynsmem;
    __half *Ash = (__half *)(dynsmem + WS_BYTES);
    __shared__ float sg[H], sbi[H], sbias[H];
    int tid = threadIdx.x, lane = tid & 31, warp = tid >> 5;
    int wm = warp >> 2, wn = warp & 3;
    if (tid < H) { sg[tid] = qf_g[tid]; sbi[tid] = qf_b[tid]; sbias[tid] = qf_bias[tid]; }
    load_weights(Wsh, hQf, tid);
    __syncthreads();
    int g0 = blockIdx.x * MT;
    for (int rr = 0; rr < 8; rr++) {
        int r = warp * 8 + rr;
        const float *q = question + (size_t)(g0 + r) * H;
        float v[8], s = 0.f, sq = 0.f;
#pragma unroll
        for (int i = 0; i < 8; i++) {
            int c = lane + 32 * i;
            float x = q[c]; v[i] = x; s += x; sq += x * x;
        }
        warpReduce2(s, sq);
        float m = s * (1.f / H), inv = rsqrtf(sq * (1.f / H) - m * m + EPS);
#pragma unroll
        for (int i = 0; i < 8; i++) {
            int c = lane + 32 * i;
            Ash[r * PA + c] = __float2half((v[i] - m) * inv * sg[c] + sbi[c]);
        }
    }
    __syncthreads();
    float acc[2][8][4];
#pragma unroll
    for (int mi = 0; mi < 2; mi++)
#pragma unroll
        for (int ni = 0; ni < 8; ni++)
            acc[mi][ni][0] = acc[mi][ni][1] = acc[mi][ni][2] = acc[mi][ni][3] = 0.f;
    mma_block(Ash, Wsh, acc, lane, wm, wn);
#pragma unroll
    for (int mi = 0; mi < 2; mi++) {
        int rb = g0 + 32 * wm + 16 * mi + (lane >> 2);
#pragma unroll
        for (int ni = 0; ni < 8; ni++) {
            int c = 64 * wn + 8 * ni + 2 * (lane & 3);
            float2 o0 = make_float2(gelu_f(acc[mi][ni][0] + sbias[c]),
                                    gelu_f(acc[mi][ni][1] + sbias[c + 1]));
            float2 o1 = make_float2(gelu_f(acc[mi][ni][2] + sbias[c]),
                                    gelu_f(acc[mi][ni][3] + sbias[c + 1]));
            *(float2 *)&g_film[(size_t)rb * H + c] = o0;
            *(float2 *)&g_film[(size_t)(rb + 8) * H + c] = o1;
        }
    }
}

// ---------------- pass1: fused 2-layer MLP, KCH=64, 2-buffer ring ----------------
__global__ __launch_bounds__(256, 2) void pass1_fused(
    const float *edge_tokens, const float *order_emb, const float *type_emb,
    const float *mlp_g, const float *mlp_b, const float *mlp_bias,
    const int *edge_batch, const int *sel_order, const void *mask) {
    __half *Ash = (__half *)dynsmem;                               // [64][PA]
    __half *Wb0 = (__half *)(dynsmem + MTE * PA * 2);              // [64][PW]
    __half *Wb1 = Wb0 + KCH * PW;
    __half *WbR[2] = {Wb0, Wb1};
    __shared__ float p_g0[H], p_b0[H], p_g1[H], p_b1[H], p_bias0[H], p_bias1[H], p_typ[H];
    __shared__ int sb[MTE], soi[MTE];
    __shared__ float smask[MTE], sS[MTE], sQ[MTE];

    int tid = threadIdx.x, lane = tid & 31, warp = tid >> 5;
    int wm = warp >> 2, wn = warp & 3;
    int mode = g_maskmode;
    int e0 = blockIdx.x * MTE;

    prefetch_chunk(WbR[0], hW0, 0, tid);   // P0, overlaps gather

    if (tid < H) {
        p_g0[tid] = mlp_g[tid]; p_b0[tid] = mlp_b[tid];
        p_g1[tid] = mlp_g[H + tid]; p_b1[tid] = mlp_b[H + tid];
        p_bias0[tid] = mlp_bias[tid]; p_bias1[tid] = mlp_bias[H + tid];
        p_typ[tid] = type_emb[2 * H + tid];
    }
    if (tid < MTE) {
        int e = e0 + tid;
        sb[tid] = edge_batch[e];
        int so = sel_order[e];
        so = so < -1 ? -1 : (so > 10 ? 10 : so);
        soi[tid] = so + 1;
        smask[tid] = mask_val(mask, e, mode);
        sS[tid] = 0.f; sQ[tid] = 0.f;
    }
    __syncthreads();

    // parallel cnt contribution (replaces serial tid==0 run-length loop)
    if (tid < MTE) atomicAdd(&g_cnt[sb[tid]], smask[tid]);

    // gather + LN0 -> Ash: lane owns 8 contiguous columns, 2 rows in flight
    int cb = lane * 8;
    float tloc[8];
#pragma unroll
    for (int i = 0; i < 8; i++) tloc[i] = p_typ[cb + i];
#pragma unroll 1
    for (int it = 0; it < 4; it++) {
        int r0 = warp * 8 + 2 * it, r1 = r0 + 1;
        float v0[8], v1[8];
        {
            const float *et = edge_tokens + (size_t)(e0 + r0) * H + cb;
            const float *fl = g_film + (size_t)sb[r0] * H + cb;
            const float *oe = order_emb + (size_t)soi[r0] * H + cb;
            float4 ea = *(const float4 *)et, eb = *(const float4 *)(et + 4);
            float4 fa = *(const float4 *)fl, fb = *(const float4 *)(fl + 4);
            float4 oa = *(const float4 *)oe, ob = *(const float4 *)(oe + 4);
            v0[0] = ea.x + fa.x + oa.x + tloc[0];
            v0[1] = ea.y + fa.y + oa.y + tloc[1];
            v0[2] = ea.z + fa.z + oa.z + tloc[2];
            v0[3] = ea.w + fa.w + oa.w + tloc[3];
            v0[4] = eb.x + fb.x + ob.x + tloc[4];
            v0[5] = eb.y + fb.y + ob.y + tloc[5];
            v0[6] = eb.z + fb.z + ob.z + tloc[6];
            v0[7] = eb.w + fb.w + ob.w + tloc[7];
        }
        {
            const float *et = edge_tokens + (size_t)(e0 + r1) * H + cb;
            const float *fl = g_film + (size_t)sb[r1] * H + cb;
            const float *oe = order_emb + (size_t)soi[r1] * H + cb;
            float4 ea = *(const float4 *)et, eb = *(const float4 *)(et + 4);
            float4 fa = *(const float4 *)fl, fb = *(const float4 *)(fl + 4);
            float4 oa = *(const float4 *)oe, ob = *(const float4 *)(oe + 4);
            v1[0] = ea.x + fa.x + oa.x + tloc[0];
            v1[1] = ea.y + fa.y + oa.y + tloc[1];
            v1[2] = ea.z + fa.z + oa.z + tloc[2];
            v1[3] = ea.w + fa.w + oa.w + tloc[3];
            v1[4] = eb.x + fb.x + ob.x + tloc[4];
            v1[5] = eb.y + fb.y + ob.y + tloc[5];
            v1[6] = eb.z + fb.z + ob.z + tloc[6];
            v1[7] = eb.w + fb.w + ob.w + tloc[7];
        }
        float s0 = 0.f, q0 = 0.f, s1 = 0.f, q1 = 0.f;
#pragma unroll
        for (int i = 0; i < 8; i++) {
            s0 += v0[i]; q0 += v0[i] * v0[i];
            s1 += v1[i]; q1 += v1[i] * v1[i];
        }
        warpReduce2(s0, q0);
        warpReduce2(s1, q1);
        float m0 = s0 * (1.f / H), i0 = rsqrtf(q0 * (1.f / H) - m0 * m0 + EPS);
        float m1 = s1 * (1.f / H), i1 = rsqrtf(q1 * (1.f / H) - m1 * m1 + EPS);
        __half2 h0[4], h1[4];
#pragma unroll
        for (int j = 0; j < 4; j++) {
            int c = cb + 2 * j;
            h0[j] = __floats2half2_rn((v0[2 * j] - m0) * i0 * p_g0[c] + p_b0[c],
                                      (v0[2 * j + 1] - m0) * i0 * p_g0[c + 1] + p_b0[c + 1]);
            h1[j] = __floats2half2_rn((v1[2 * j] - m1) * i1 * p_g0[c] + p_b0[c],
                                      (v1[2 * j + 1] - m1) * i1 * p_g0[c + 1] + p_b0[c + 1]);
        }
        *(uint4 *)(Ash + r0 * PA + cb) = *(uint4 *)h0;
        *(uint4 *)(Ash + r1 * PA + cb) = *(uint4 *)h1;
    }

    // hoisted ldmatrix base addresses
    unsigned aB0 = s2u(Ash + (32 * wm + (lane & 15)) * PA + ((lane >> 4) << 3));
    unsigned aB1 = s2u(Ash + (32 * wm + 16 + (lane & 15)) * PA + ((lane >> 4) << 3));
    unsigned bB[2];
#pragma unroll
    for (int t = 0; t < 2; t++)
        bB[t] = s2u(WbR[t] + (lane & 15) * PW + 64 * wn + ((lane >> 4) << 3));

    float acc[2][8][4];
#pragma unroll
    for (int mi = 0; mi < 2; mi++)
#pragma unroll
        for (int ni = 0; ni < 8; ni++) {
            int c = 64 * wn + 8 * ni + 2 * (lane & 3);
            acc[mi][ni][0] = p_bias0[c];     acc[mi][ni][1] = p_bias0[c + 1];
            acc[mi][ni][2] = p_bias0[c];     acc[mi][ni][3] = p_bias0[c + 1];
        }
    // W0 chunk loop: 2-buffer, one sync per chunk
#pragma unroll 1
    for (int kc = 0; kc < NCH; kc++) {
        CP_WAIT0();
        __syncthreads();
        if (kc + 1 < NCH) prefetch_chunk(WbR[(kc + 1) & 1], hW0, kc + 1, tid);
        mma_chunk64(aB0, aB1, bB[kc & 1], acc, kc);
    }
    __syncthreads();
    prefetch_chunk(WbR[0], hW1, 0, tid);   // W1 P0

    // epilogue: gelu + LN1 stats
    float ps[2][2], pq[2][2];
#pragma unroll
    for (int mi = 0; mi < 2; mi++) { ps[mi][0] = ps[mi][1] = pq[mi][0] = pq[mi][1] = 0.f; }
#pragma unroll
    for (int mi = 0; mi < 2; mi++)
#pragma unroll
        for (int ni = 0; ni < 8; ni++)
#pragma unroll
            for (int hh = 0; hh < 2; hh++) {
                float v0 = gelu_f(acc[mi][ni][2 * hh]);
                float v1 = gelu_f(acc[mi][ni][2 * hh + 1]);
                acc[mi][ni][2 * hh] = v0; acc[mi][ni][2 * hh + 1] = v1;
                ps[mi][hh] += v0 + v1;
                pq[mi][hh] += v0 * v0 + v1 * v1;
            }
#pragma unroll
    for (int mi = 0; mi < 2; mi++)
#pragma unroll
        for (int hh = 0; hh < 2; hh++) {
            float s = quad_reduce(ps[mi][hh]);
            float q = quad_reduce(pq[mi][hh]);
            if ((lane & 3) == 0) {
                int r = 32 * wm + 16 * mi + 8 * hh + (lane >> 2);
                atomicAdd(&sS[r], s);
                atomicAdd(&sQ[r], q);
            }
        }
    __syncthreads();
    // normalize -> Ash (fp16), becomes A for layer 1
#pragma unroll
    for (int mi = 0; mi < 2; mi++)
#pragma unroll
        for (int hh = 0; hh < 2; hh++) {
            int r = 32 * wm + 16 * mi + 8 * hh + (lane >> 2);
            float m = sS[r] * (1.f / H);
            float inv = rsqrtf(sQ[r] * (1.f / H) - m * m + EPS);
#pragma unroll
            for (int ni = 0; ni < 8; ni++) {
                int c = 64 * wn + 8 * ni + 2 * (lane & 3);
                float n0 = (acc[mi][ni][2 * hh] - m) * inv * p_g1[c] + p_b1[c];
                float n1 = (acc[mi][ni][2 * hh + 1] - m) * inv * p_g1[c + 1] + p_b1[c + 1];
                *(__half2 *)&Ash[r * PA + c] = __floats2half2_rn(n0, n1);
            }
        }

#pragma unroll
    for (int mi = 0; mi < 2; mi++)
#pragma unroll
        for (int ni = 0; ni < 8; ni++) {
            int c = 64 * wn + 8 * ni + 2 * (lane & 3);
            acc[mi][ni][0] = p_bias1[c];     acc[mi][ni][1] = p_bias1[c + 1];
            acc[mi][ni][2] = p_bias1[c];     acc[mi][ni][3] = p_bias1[c + 1];
        }
    // W1 chunk loop
#pragma unroll 1
    for (int kc = 0; kc < NCH; kc++) {
        CP_WAIT0();
        __syncthreads();
        if (kc + 1 < NCH) prefetch_chunk(WbR[(kc + 1) & 1], hW1, kc + 1, tid);
        mma_chunk64(aB0, aB1, bB[kc & 1], acc, kc);
    }

    // x = gelu(acc) -> Ash : each warp writes only rows it owns (own acc),
    // but rows it owns were written by *other* warps' ldmatrix reads —
    // need all warps done reading Ash before overwriting: one sync.
    __syncthreads();
#pragma unroll
    for (int mi = 0; mi < 2; mi++)
#pragma unroll
        for (int hh = 0; hh < 2; hh++) {
            int r = 32 * wm + 16 * mi + 8 * hh + (lane >> 2);
#pragma unroll
            for (int ni = 0; ni < 8; ni++) {
                int c = 64 * wn + 8 * ni + 2 * (lane & 3);
                *(__half2 *)&Ash[r * PA + c] = __floats2half2_rn(
                    gelu_f(acc[mi][ni][2 * hh]), gelu_f(acc[mi][ni][2 * hh + 1]));
            }
        }
    __syncthreads();
    // write g_xh coalesced (2048 uint4)
#pragma unroll
    for (int it = 0; it < 8; it++) {
        int idx = tid + 256 * it;
        int row = idx >> 5, q = idx & 31;
        *(uint4 *)(g_xh + (size_t)(e0 + row) * H + q * 8) =
            *(const uint4 *)(Ash + row * PA + q * 8);
    }
    // masked scatter (sorted -> run-length); thread = column
    {
        float accs = 0.f;
        int bprev = sb[0];
        for (int r = 0; r < MTE; r++) {
            int b = sb[r];
            if (b != bprev) {
                atomicAdd(&g_selsum[bprev * H + tid], accs);
                accs = 0.f;
                bprev = b;
            }
            accs += smask[r] * __half2float(Ash[r * PA + tid]);
        }
        atomicAdd(&g_selsum[bprev * H + tid], accs);
    }
}

// ---------------- graphA: cur / stats / cg / zn ----------------
__global__ void graphA(const float *question, const float *gn_g,
                       const float *gn_b, const float *lh_g, const float *sp_g,
                       const float *sp_b, float *out_cur) {
    int g = blockIdx.x, j = threadIdx.x;
    float q = question[g * H + j];
    float cnt = g_cnt[g];
    float pre = g_selsum[g * H + j] / fmaxf(cnt, 1.f) + q;
    float s = pre, sq = pre * pre;
    blockReduce2(s, sq);
    float m = s * (1.f / H);
    float v = sq * (1.f / H) - m * m;
    float inv = rsqrtf(v + EPS);
    float cur = (pre - m) * inv * gn_g[j] + gn_b[j];
    out_cur[g * H + j] = cur;
    g_cg[g * H + j] = __float2half(cur * lh_g[j]);

    float cs = cur, csq = cur * cur;
    blockReduce2(cs, csq);
    if (j == 0) { g_cs[g] = cs; g_csq[g] = csq; }

    float qs = q, qsq = q * q;
    blockReduce2(qs, qsq);

    float m5 = (cs + qs) * (1.f / H2);
    float v5 = (csq + qsq) * (1.f / H2) - m5 * m5;
    float i5 = rsqrtf(v5 + EPS);
    g_zn[(size_t)g * H2 + j] = __float2half((cur - m5) * i5 * sp_g[j] + sp_b[j]);
    g_zn[(size_t)g * H2 + H + j] = __float2half((q - m5) * i5 * sp_g[H + j] + sp_b[H + j]);
}

// ---------------- pcstop: Pc (blocks 0..15) + stop head (blocks 16..31) ----------------
__global__ __launch_bounds__(NTH, 1) void pcstop_mma(const float *sp_b1,
                                                     const float *sp_W2,
                                                     const float *sp_b2,
                                                     float *out_stop) {
    __half *Wsh = (__half *)dynsmem;
    __half *Ash = (__half *)(dynsmem + WS_BYTES);
    int tid = threadIdx.x, lane = tid & 31, warp = tid >> 5;
    int wm = warp >> 2, wn = warp & 3;

    if (blockIdx.x < NT_G) {
        load_weights(Wsh, hPcW, tid);
        int g0 = blockIdx.x * MT;
#pragma unroll
        for (int it = 0; it < 8; it++) {
            int idx = tid + NTH * it;
            int row = idx >> 5, q = idx & 31;
            *(uint4 *)(Ash + row * PA + q * 8) =
                *(const uint4 *)(g_cg + (size_t)(g0 + row) * H + q * 8);
        }
        __syncthreads();
        float acc[2][8][4];
#pragma unroll
        for (int mi = 0; mi < 2; mi++)
#pragma unroll
            for (int ni = 0; ni < 8; ni++)
                acc[mi][ni][0] = acc[mi][ni][1] = acc[mi][ni][2] = acc[mi][ni][3] = 0.f;
        mma_block(Ash, Wsh, acc, lane, wm, wn);
#pragma unroll
        for (int mi = 0; mi < 2; mi++) {
            int rb = g0 + 32 * wm + 16 * mi + (lane >> 2);
#pragma unroll
            for (int ni = 0; ni < 8; ni++) {
                int c = 64 * wn + 8 * ni + 2 * (lane & 3);
                *(float2 *)&g_Pc[(size_t)rb * H + c] = make_float2(acc[mi][ni][0], acc[mi][ni][1]);
                *(float2 *)&g_Pc[(size_t)(rb + 8) * H + c] = make_float2(acc[mi][ni][2], acc[mi][ni][3]);
            }
        }
    } else {
        __shared__ float sb1[H], sw2[H], srow[MT];
        if (tid < H) { sb1[tid] = sp_b1[tid]; sw2[tid] = sp_W2[tid]; }
        if (tid < MT) srow[tid] = 0.f;
        int g0 = (blockIdx.x - NT_G) * MT;
        float acc[2][8][4];
#pragma unroll
        for (int mi = 0; mi < 2; mi++)
#pragma unroll
            for (int ni = 0; ni < 8; ni++)
                acc[mi][ni][0] = acc[mi][ni][1] = acc[mi][ni][2] = acc[mi][ni][3] = 0.f;
        for (int kc = 0; kc < 2; kc++) {
            __syncthreads();
            load_weights(Wsh, hSpW + kc * H * H, tid);
#pragma unroll
            for (int it = 0; it < 8; it++) {
                int idx = tid + NTH * it;
                int row = idx >> 5, q = idx & 31;
                *(uint4 *)(Ash + row * PA + q * 8) =
                    *(const uint4 *)(g_zn + (size_t)(g0 + row) * H2 + kc * H + q * 8);
            }
            __syncthreads();
            mma_block(Ash, Wsh, acc, lane, wm, wn);
        }
#pragma unroll
        for (int mi = 0; mi < 2; mi++)
#pragma unroll
            for (int hh = 0; hh < 2; hh++) {
                float sum = 0.f;
#pragma unroll
                for (int ni = 0; ni < 8; ni++) {
                    int c = 64 * wn + 8 * ni + 2 * (lane & 3);
                    sum += gelu_f(acc[mi][ni][2 * hh] + sb1[c]) * sw2[c];
                    sum += gelu_f(acc[mi][ni][2 * hh + 1] + sb1[c + 1]) * sw2[c + 1];
                }
                sum = quad_reduce(sum);
                if ((lane & 3) == 0) {
                    int r = 32 * wm + 16 * mi + 8 * hh + (lane >> 2);
                    atomicAdd(&srow[r], sum);
                }
            }
        __syncthreads();
        if (tid < MT) out_stop[g0 + tid] = srow[tid] + sp_b2[0];
    }
}

// ---------------- pass2: nxt LN -> @Wh (KCH=64, 2-buf) -> head epilogue ----------------
__global__ __launch_bounds__(256, 2) void pass2_str(const float *question,
                                                    const float *gn_g,
                                                    const float *gn_b,
                                                    const float *lh_W2,
                                                    const float *lh_b2,
                                                    const int *edge_batch,
                                                    float *out_edge) {
    __half *Ash = (__half *)dynsmem;
    __half *Wb0 = (__half *)(dynsmem + MTE * PA * 2);
    __half *Wb1 = Wb0 + KCH * PW;
    __half *WbR[2] = {Wb0, Wb1};
    __shared__ float sg[H], sbt[H], svg[H], svb[H], sw2n[H];
    __shared__ int sb[MTE];
    __shared__ float srm[MTE], sri[MTE], srow[MTE];
    int tid = threadIdx.x, lane = tid & 31, warp = tid >> 5;
    int wm = warp >> 2, wn = warp & 3;
    int e0 = blockIdx.x * MTE;

    prefetch_chunk(WbR[0], hWh, 0, tid);

    if (tid < H) {
        sg[tid] = gn_g[tid]; sbt[tid] = gn_b[tid];
        svg[tid] = g_vg[tid]; svb[tid] = g_vb[tid];
        sw2n[tid] = lh_W2[tid];
    }
    if (tid < MTE) {
        sb[tid] = edge_batch[e0 + tid];
        srow[tid] = 0.f;
    }
    float b2v = lh_b2[0];
    __syncthreads();

    // gather + LN -> Ash: lane owns 8 contiguous cols, 2 rows in flight
    int cb = lane * 8;
#pragma unroll 1
    for (int it = 0; it < 4; it++) {
        int r0 = warp * 8 + 2 * it, r1 = r0 + 1;
        float v0[8], v1[8];
        {
            int b = sb[r0];
            float invc = 1.f / (g_cnt[b] + 1.f);
            const float *ss = g_selsum + (size_t)b * H + cb;
            const __half *xh = g_xh + (size_t)(e0 + r0) * H + cb;
            const float *q = question + (size_t)b * H + cb;
            float4 sa = *(const float4 *)ss, sbv = *(const float4 *)(ss + 4);
            float4 qa = *(const float4 *)q, qb = *(const float4 *)(q + 4);
            uint4 hx = *(const uint4 *)xh;
            __half2 *hp = (__half2 *)&hx;
            float2 x0 = __half22float2(hp[0]), x1 = __half22float2(hp[1]);
            float2 x2 = __half22float2(hp[2]), x3 = __half22float2(hp[3]);
            v0[0] = (sa.x + x0.x) * invc + qa.x;
            v0[1] = (sa.y + x0.y) * invc + qa.y;
            v0[2] = (sa.z + x1.x) * invc + qa.z;
            v0[3] = (sa.w + x1.y) * invc + qa.w;
            v0[4] = (sbv.x + x2.x) * invc + qb.x;
            v0[5] = (sbv.y + x2.y) * invc + qb.y;
            v0[6] = (sbv.z + x3.x) * invc + qb.z;
            v0[7] = (sbv.w + x3.y) * invc + qb.w;
        }
        {
            int b = sb[r1];
            float invc = 1.f / (g_cnt[b] + 1.f);
            const float *ss = g_selsum + (size_t)b * H + cb;
            const __half *xh = g_xh + (size_t)(e0 + r1) * H + cb;
            const float *q = question + (size_t)b * H + cb;
            float4 sa = *(const float4 *)ss, sbv = *(const float4 *)(ss + 4);
            float4 qa = *(const float4 *)q, qb = *(const float4 *)(q + 4);
            uint4 hx = *(const uint4 *)xh;
            __half2 *hp = (__half2 *)&hx;
            float2 x0 = __half22float2(hp[0]), x1 = __half22float2(hp[1]);
            float2 x2 = __half22float2(hp[2]), x3 = __half22float2(hp[3]);
            v1[0] = (sa.x + x0.x) * invc + qa.x;
            v1[1] = (sa.y + x0.y) * invc + qa.y;
            v1[2] = (sa.z + x1.x) * invc + qa.z;
            v1[3] = (sa.w + x1.y) * invc + qa.w;
            v1[4] = (sbv.x + x2.x) * invc + qb.x;
            v1[5] = (sbv.y + x2.y) * invc + qb.y;
            v1[6] = (sbv.z + x3.x) * invc + qb.z;
            v1[7] = (sbv.w + x3.y) * invc + qb.w;
        }
        float s0 = 0.f, q0 = 0.f, s1 = 0.f, q1 = 0.f;
#pragma unroll
        for (int i = 0; i < 8; i++) {
            s0 += v0[i]; q0 += v0[i] * v0[i];
            s1 += v1[i]; q1 += v1[i] * v1[i];
        }
        warpReduce2(s0, q0);
        warpReduce2(s1, q1);
        float m0 = s0 * (1.f / H), i0 = rsqrtf(q0 * (1.f / H) - m0 * m0 + EPS);
        float m1 = s1 * (1.f / H), i1 = rsqrtf(q1 * (1.f / H) - m1 * m1 + EPS);
        float s20 = 0.f, sq20 = 0.f, s21 = 0.f, sq21 = 0.f;
        __half2 h0[4], h1[4];
#pragma unroll
        for (int j = 0; j < 4; j++) {
            int c = cb + 2 * j;
            float n00 = (v0[2 * j] - m0) * i0 * sg[c] + sbt[c];
            float n01 = (v0[2 * j + 1] - m0) * i0 * sg[c + 1] + sbt[c + 1];
            float n10 = (v1[2 * j] - m1) * i1 * sg[c] + sbt[c];
            float n11 = (v1[2 * j + 1] - m1) * i1 * sg[c + 1] + sbt[c + 1];
            s20 += n00 + n01; sq20 += n00 * n00 + n01 * n01;
            s21 += n10 + n11; sq21 += n10 * n10 + n11 * n11;
            h0[j] = __floats2half2_rn(n00, n01);
            h1[j] = __floats2half2_rn(n10, n11);
        }
        *(uint4 *)(Ash + r0 * PA + cb) = *(uint4 *)h0;
        *(uint4 *)(Ash + r1 * PA + cb) = *(uint4 *)h1;
        warpReduce2(s20, sq20);
        warpReduce2(s21, sq21);
        if (lane == 0) {
            int b0g = sb[r0], b1g = sb[r1];
            float M0 = (g_cs[b0g] + s20) * (1.f / H2);
            float V0 = (g_csq[b0g] + sq20) * (1.f / H2) - M0 * M0;
            srm[r0] = M0; sri[r0] = rsqrtf(V0 + EPS);
            float M1 = (g_cs[b1g] + s21) * (1.f / H2);
            float V1 = (g_csq[b1g] + sq21) * (1.f / H2) - M1 * M1;
            srm[r1] = M1; sri[r1] = rsqrtf(V1 + EPS);
        }
    }

    unsigned aB0 = s2u(Ash + (32 * wm + (lane & 15)) * PA + ((lane >> 4) << 3));
    unsigned aB1 = s2u(Ash + (32 * wm + 16 + (lane & 15)) * PA + ((lane >> 4) << 3));
    unsigned bB[2];
#pragma unroll
    for (int t = 0; t < 2; t++)
        bB[t] = s2u(WbR[t] + (lane & 15) * PW + 64 * wn + ((lane >> 4) << 3));

    float acc[2][8][4];
#pragma unroll
    for (int mi = 0; mi < 2; mi++)
#pragma unroll
        for (int ni = 0; ni < 8; ni++)
            acc[mi][ni][0] = acc[mi][ni][1] = acc[mi][ni][2] = acc[mi][ni][3] = 0.f;
#pragma unroll 1
    for (int kc = 0; kc < NCH; kc++) {
        CP_WAIT0();
        __syncthreads();
        if (kc + 1 < NCH) prefetch_chunk(WbR[(kc + 1) & 1], hWh, kc + 1, tid);
        mma_chunk64(aB0, aB1, bB[kc & 1], acc, kc);
    }

#pragma unroll
    for (int mi = 0; mi < 2; mi++)
#pragma unroll
        for (int hh = 0; hh < 2; hh++) {
            int r = 32 * wm + 16 * mi + 8 * hh + (lane >> 2);
            float rm = srm[r], ri = sri[r];
            int bg = sb[r];
            float sum = 0.f;
#pragma unroll
            for (int ni = 0; ni < 8; ni++) {
                int c = 64 * wn + 8 * ni + 2 * (lane & 3);
                float2 pc = *(const float2 *)&g_Pc[(size_t)bg * H + c];
                float h0 = (pc.x + acc[mi][ni][2 * hh] - rm * svg[c]) * ri + svb[c];
                float h1 = (pc.y + acc[mi][ni][2 * hh + 1] - rm * svg[c + 1]) * ri + svb[c + 1];
                sum += gelu_f(h0) * sw2n[c] + gelu_f(h1) * sw2n[c + 1];
            }
            sum = quad_reduce(sum);
            if ((lane & 3) == 0) atomicAdd(&srow[r], sum);
        }
    __syncthreads();
    if (tid < MTE) out_edge[e0 + tid] = srow[tid] + b2v;
}

// ---------------- launch ----------------
extern "C" void kernel_launch(void *const *d_in, const int *in_sizes, int n_in,
                              void *d_out, int out_size) {
    const float *edge_tokens = (const float *)d_in[0];
    const float *question = (const float *)d_in[1];
    const float *order_emb = (const float *)d_in[2];
    const float *type_emb = (const float *)d_in[3];
    const float *gn_g = (const float *)d_in[4];
    const float *gn_b = (const float *)d_in[5];
    const float *qf_g = (const float *)d_in[6];
    const float *qf_b = (const float *)d_in[7];
    const float *qf_W = (const float *)d_in[8];
    const float *qf_bias = (const float *)d_in[9];
    const float *mlp_g = (const float *)d_in[10];
    const float *mlp_b = (const float *)d_in[11];
    const float *mlp_W = (const float *)d_in[12];
    const float *mlp_bias = (const float *)d_in[13];
    const float *lh_g = (const float *)d_in[14];
    const float *lh_b = (const float *)d_in[15];
    const float *lh_W1 = (const float *)d_in[16];
    const float *lh_b1 = (const float *)d_in[17];
    const float *lh_W2 = (const float *)d_in[18];
    const float *lh_b2 = (const float *)d_in[19];
    const float *sp_g = (const float *)d_in[20];
    const float *sp_b = (const float *)d_in[21];
    const float *sp_W1 = (const float *)d_in[22];
    const float *sp_b1 = (const float *)d_in[23];
    const float *sp_W2 = (const float *)d_in[24];
    const float *sp_b2 = (const float *)d_in[25];
    const int *edge_batch = (const int *)d_in[26];
    const void *sel_mask = (const void *)d_in[27];
    const int *sel_order = (const int *)d_in[28];

    float *out_edge = (float *)d_out;
    float *out_stop = out_edge + E;
    float *out_cur = out_stop + G;

    cudaFuncSetAttribute(film_mma, cudaFuncAttributeMaxDynamicSharedMemorySize, DSMEM_G);
    cudaFuncSetAttribute(pcstop_mma, cudaFuncAttributeMaxDynamicSharedMemorySize, DSMEM_G);
    cudaFuncSetAttribute(pass1_fused, cudaFuncAttributeMaxDynamicSharedMemorySize, DSMEM_E);
    cudaFuncSetAttribute(pass2_str, cudaFuncAttributeMaxDynamicSharedMemorySize, DSMEM_E);

    prep_half2<<<7 * 256, 256>>>(qf_W, mlp_W, lh_g, lh_W1, sp_W1);
    film_mma<<<NT_G, NTH, DSMEM_G>>>(question, qf_g, qf_b, qf_bias);
    sniffzero_kernel<<<(G * H + 255) / 256, 256>>>(sel_mask);
    pass1_fused<<<E / MTE, 256, DSMEM_E>>>(edge_tokens, order_emb, type_emb,
                                           mlp_g, mlp_b, mlp_bias, edge_batch,
                                           sel_order, sel_mask);
    prep_vg<<<16, 256>>>(lh_g, lh_b, lh_W1, lh_b1);
    graphA<<<G, 256>>>(question, gn_g, gn_b, lh_g, sp_g, sp_b, out_cur);
    pcstop_mma<<<2 * NT_G, NTH, DSMEM_G>>>(sp_b1, sp_W2, sp_b2, out_stop);
    pass2_str<<<E / MTE, 256, DSMEM_E>>>(question, gn_g, gn_b, lh_W2, lh_b2,
                                         edge_batch, out_edge);
}

// round 16
// speedup vs baseline: 1.1188x; 1.1188x over previous
#include <cuda_runtime.h>
#include <cuda_fp16.h>
#include <stdint.h>
#include <math.h>

// Problem constants
#define H 256
#define H2 512
#define G 2048
#define E 262144
#define EPS 1e-5f
#define MT 128          // rows per tile (graph-side mma kernels)
#define MTE 64          // rows per tile (edge-side streamed kernels)
#define PA 264          // A-tile row stride (halves)
#define PW 264          // W-tile row stride (halves)
#define KCH 64          // K rows per streamed chunk
#define NCH 4           // chunks per 256-K matmul
#define NTH 512         // threads for graph-side mma kernels
#define NT_G (G / MT)   // 16 graph tiles

// ---------------- device scratch (16B aligned: vector access) ----------------
__device__ __align__(16) float  g_film[G * H];
__device__ __align__(16) __half g_xh[(size_t)E * H];   // MLP out (x)
__device__ __align__(16) float  g_selsum[G * H];
__device__ __align__(16) float  g_cnt[G];
__device__ __align__(16) float  g_Pc[G * H];
__device__ __align__(16) float  g_cs[G], g_csq[G];
__device__ __align__(16) float  g_vg[H], g_vb[H];
__device__ __align__(16) __half g_cg[G * H];           // cur * lh_g_lo
__device__ __align__(16) __half g_zn[G * H2];          // stop-head LN512 out
__device__ __align__(16) __half hQf[H * H];
__device__ __align__(16) __half hW0[H * H];
__device__ __align__(16) __half hW1[H * H];
__device__ __align__(16) __half hWh[H * H];
__device__ __align__(16) __half hPcW[H * H];
__device__ __align__(16) __half hSpW[H2 * H];
__device__ int g_maskmode;

// ---------------- helpers ----------------
// Fast gelu: sigmoid form of tanh approximation.
// gelu(x) ~= x * sigmoid(1.5957691216*(x + 0.044715 x^3))
// = x / (1 + exp(-u)); saturation-safe at both tails.
__device__ __forceinline__ float gelu_f(float x) {
    float x2 = x * x;
    float u = 1.5957691216f * x * fmaf(0.044715f, x2, 1.0f);
    return __fdividef(x, 1.0f + __expf(-u));
}

__device__ __forceinline__ void warpReduce2(float &a, float &b) {
#pragma unroll
    for (int o = 16; o; o >>= 1) {
        a += __shfl_xor_sync(0xffffffffu, a, o);
        b += __shfl_xor_sync(0xffffffffu, b, o);
    }
}

// 256-thread block reduce (graphA only)
__device__ __forceinline__ void blockReduce2(float &a, float &b) {
    __shared__ float sa[8], sbx[8];
    int lane = threadIdx.x & 31, wid = threadIdx.x >> 5;
    warpReduce2(a, b);
    if (lane == 0) { sa[wid] = a; sbx[wid] = b; }
    __syncthreads();
    if (wid == 0) {
        a = (lane < 8) ? sa[lane] : 0.f;
        b = (lane < 8) ? sbx[lane] : 0.f;
#pragma unroll
        for (int o = 4; o; o >>= 1) {
            a += __shfl_xor_sync(0xffffffffu, a, o);
            b += __shfl_xor_sync(0xffffffffu, b, o);
        }
        if (lane == 0) { sa[0] = a; sbx[0] = b; }
    }
    __syncthreads();
    a = sa[0]; b = sbx[0];
    __syncthreads();
}

__device__ __forceinline__ float quad_reduce(float x) {
    x += __shfl_xor_sync(0xffffffffu, x, 1);
    x += __shfl_xor_sync(0xffffffffu, x, 2);
    return x;
}

__device__ __forceinline__ float mask_val(const void *p, int e, int mode) {
    if (mode == 0) return ((const int *)p)[e] != 0 ? 1.f : 0.f;
    if (mode == 1) return ((const float *)p)[e] != 0.f ? 1.f : 0.f;
    return ((const unsigned char *)p)[e] != 0 ? 1.f : 0.f;
}

__device__ __forceinline__ unsigned int s2u(const void *p) {
    return (unsigned int)__cvta_generic_to_shared(p);
}

__device__ __forceinline__ void ldm_x4(unsigned int &r0, unsigned int &r1,
                                       unsigned int &r2, unsigned int &r3,
                                       unsigned int addr) {
    asm volatile("ldmatrix.sync.aligned.m8n8.x4.shared.b16 {%0,%1,%2,%3}, [%4];"
                 : "=r"(r0), "=r"(r1), "=r"(r2), "=r"(r3) : "r"(addr));
}
__device__ __forceinline__ void ldm_x4_t(unsigned int &r0, unsigned int &r1,
                                         unsigned int &r2, unsigned int &r3,
                                         unsigned int addr) {
    asm volatile("ldmatrix.sync.aligned.m8n8.x4.trans.shared.b16 {%0,%1,%2,%3}, [%4];"
                 : "=r"(r0), "=r"(r1), "=r"(r2), "=r"(r3) : "r"(addr));
}
__device__ __forceinline__ void mma16816(float *c, unsigned int a0,
                                         unsigned int a1, unsigned int a2,
                                         unsigned int a3, unsigned int b0,
                                         unsigned int b1) {
    asm volatile(
        "mma.sync.aligned.m16n8k16.row.col.f32.f16.f16.f32 "
        "{%0,%1,%2,%3}, {%4,%5,%6,%7}, {%8,%9}, {%0,%1,%2,%3};"
        : "+f"(c[0]), "+f"(c[1]), "+f"(c[2]), "+f"(c[3])
        : "r"(a0), "r"(a1), "r"(a2), "r"(a3), "r"(b0), "r"(b1));
}

__device__ __forceinline__ void cp16(unsigned int saddr, const void *g) {
    asm volatile("cp.async.cg.shared.global [%0], [%1], 16;"
                 :: "r"(saddr), "l"(g) : "memory");
}
#define CP_COMMIT() asm volatile("cp.async.commit_group;" ::: "memory")
#define CP_WAIT0() asm volatile("cp.async.wait_group 0;" ::: "memory")

// ---- 16-warp graph-side mainloop: [128x256] @ [256x256], weights resident ----
__device__ __forceinline__ void mma_block(const __half *__restrict__ Ash,
                                          const __half *__restrict__ Wsh,
                                          float (&acc)[2][8][4], int lane,
                                          int wm, int wn) {
#pragma unroll 1
    for (int ks = 0; ks < 16; ks++) {
        unsigned int a[2][4];
#pragma unroll
        for (int mi = 0; mi < 2; mi++) {
            ldm_x4(a[mi][0], a[mi][1], a[mi][2], a[mi][3],
                   s2u(Ash + (32 * wm + 16 * mi + (lane & 15)) * PA + ks * 16 +
                       ((lane >> 4) << 3)));
        }
#pragma unroll
        for (int bi = 0; bi < 4; bi++) {
            unsigned int b0, b1, b2, b3;
            ldm_x4_t(b0, b1, b2, b3,
                     s2u(Wsh + (ks * 16 + (lane & 15)) * PW + 64 * wn + 16 * bi +
                         ((lane >> 4) << 3)));
#pragma unroll
            for (int mi = 0; mi < 2; mi++) {
                mma16816(acc[mi][2 * bi], a[mi][0], a[mi][1], a[mi][2], a[mi][3], b0, b1);
                mma16816(acc[mi][2 * bi + 1], a[mi][0], a[mi][1], a[mi][2], a[mi][3], b2, b3);
            }
        }
    }
}

// ---- edge-side chunk mainloop (KCH=64): 4 unrolled k-steps, hoisted bases ----
__device__ __forceinline__ void mma_chunk64(unsigned a0b, unsigned a1b,
                                            unsigned bb, float (&acc)[2][8][4],
                                            int kc) {
#pragma unroll
    for (int ks2 = 0; ks2 < 4; ks2++) {
        unsigned aoff = (unsigned)((kc * 4 + ks2) * 32);   // 16 halves = 32 B
        unsigned int a[2][4];
        ldm_x4(a[0][0], a[0][1], a[0][2], a[0][3], a0b + aoff);
        ldm_x4(a[1][0], a[1][1], a[1][2], a[1][3], a1b + aoff);
        unsigned bb2 = bb + (unsigned)(ks2 * (16 * PW * 2));
#pragma unroll
        for (int bi = 0; bi < 4; bi++) {
            unsigned int b0, b1, b2, b3;
            ldm_x4_t(b0, b1, b2, b3, bb2 + (unsigned)(bi * 32));
#pragma unroll
            for (int mi = 0; mi < 2; mi++) {
                mma16816(acc[mi][2 * bi], a[mi][0], a[mi][1], a[mi][2], a[mi][3], b0, b1);
                mma16816(acc[mi][2 * bi + 1], a[mi][0], a[mi][1], a[mi][2], a[mi][3], b2, b3);
            }
        }
    }
}

// prefetch one 64x256 weight chunk into smem via cp.async (2048 uint4, 256 thr)
__device__ __forceinline__ void prefetch_chunk(__half *Wc, const __half *Wg,
                                               int kc, int tid) {
    const __half *src = Wg + (size_t)kc * KCH * 256;
#pragma unroll
    for (int it = 0; it < 8; it++) {
        int idx = tid + 256 * it;       // 0..2047
        int row = idx >> 5, q = idx & 31;
        cp16(s2u(Wc + row * PW + q * 8), src + row * 256 + q * 8);
    }
    CP_COMMIT();
}

// load a 256x256 fp16 weight matrix into padded smem (8192 uint4, 512 threads)
__device__ __forceinline__ void load_weights(__half *Wsh, const __half *Wg, int tid) {
#pragma unroll
    for (int it = 0; it < 16; it++) {
        int idx = tid + NTH * it;
        int row = idx >> 5, q = idx & 31;
        *(uint4 *)(Wsh + row * PW + q * 8) = *(const uint4 *)(Wg + row * 256 + q * 8);
    }
}

extern __shared__ __align__(16) char dynsmem[];
#define WS_BYTES (256 * PW * 2)
#define DSMEM_G (WS_BYTES + MT * PA * 2)
#define DSMEM_E (MTE * PA * 2 + 2 * KCH * PW * 2)

// ---------------- K0: sniff + zero fused ----------------
__global__ void sniffzero_kernel(const void *mask) {
    if (blockIdx.x == 0) {
        const unsigned int *w = (const unsigned int *)mask;
        int i32ok = 1, f32ok = 1;
        for (int i = threadIdx.x; i < 4096; i += 256) {
            unsigned int x = w[i];
            if (x > 1u) i32ok = 0;
            float f = __uint_as_float(x);
            if (!(f == 0.f || f == 1.f)) f32ok = 0;
        }
        int all_i32 = __syncthreads_and(i32ok);
        int all_f32 = __syncthreads_and(f32ok);
        if (threadIdx.x == 0) g_maskmode = all_i32 ? 0 : (all_f32 ? 1 : 2);
    }
    int i = blockIdx.x * blockDim.x + threadIdx.x;
    if (i < G * H) g_selsum[i] = 0.f;
    if (i < G) g_cnt[i] = 0.f;
    if (i < H) { g_vg[i] = 0.f; g_vb[i] = 0.f; }
}

// ---------------- K2a: vg / vb (parallel atomic reduction, 16 blocks) ----------------
__global__ void prep_vg(const float *lh_g, const float *lh_b,
                        const float *lh_W1, const float *lh_b1) {
    int j = threadIdx.x;
    int k0 = blockIdx.x * 32;
    float a = 0.f, b = 0.f;
#pragma unroll
    for (int kk = 0; kk < 32; kk++) {
        int k = k0 + kk;
        float w = lh_W1[k * H + j];
        a += lh_g[k] * w;
        b += lh_b[k] * w;
    }
    atomicAdd(&g_vg[j], a);
    if (blockIdx.x == 0) b += lh_b1[j];
    atomicAdd(&g_vb[j], b);
}

// ---------------- K2b: fp16 weight conversion ----------------
__global__ void prep_half2(const float *qf_W, const float *mlp_W,
                           const float *lh_g, const float *lh_W1,
                           const float *sp_W1) {
    int i = blockIdx.x * 256 + threadIdx.x;
    int seg = i >> 16, off = i & 65535;
    switch (seg) {
        case 0: hQf[off] = __float2half(qf_W[off]); break;
        case 1: hW0[off] = __float2half(mlp_W[off]); break;
        case 2: hW1[off] = __float2half(mlp_W[65536 + off]); break;
        case 3: {
            int k = off >> 8;
            hWh[off] = __float2half(lh_g[H + k] * lh_W1[(H + k) * H + (off & 255)]);
        } break;
        case 4: hPcW[off] = __float2half(lh_W1[off]); break;
        case 5: hSpW[off] = __float2half(sp_W1[off]); break;
        case 6: hSpW[65536 + off] = __float2half(sp_W1[65536 + off]); break;
    }
}

// ---------------- film: g_film = gelu(LN(question)@qf_W + qf_bias) ----------------
__global__ __launch_bounds__(NTH, 1) void film_mma(const float *question,
                                                   const float *qf_g,
                                                   const float *qf_b,
                                                   const float *qf_bias) {
    __half *Wsh = (__half *)dynsmem;
    __half *Ash = (__half *)(dynsmem + WS_BYTES);
    __shared__ float sg[H], sbi[H], sbias[H];
    int tid = threadIdx.x, lane = tid & 31, warp = tid >> 5;
    int wm = warp >> 2, wn = warp & 3;
    if (tid < H) { sg[tid] = qf_g[tid]; sbi[tid] = qf_b[tid]; sbias[tid] = qf_bias[tid]; }
    load_weights(Wsh, hQf, tid);
    __syncthreads();
    int g0 = blockIdx.x * MT;
    for (int rr = 0; rr < 8; rr++) {
        int r = warp * 8 + rr;
        const float *q = question + (size_t)(g0 + r) * H;
        float v[8], s = 0.f, sq = 0.f;
#pragma unroll
        for (int i = 0; i < 8; i++) {
            int c = lane + 32 * i;
            float x = q[c]; v[i] = x; s += x; sq += x * x;
        }
        warpReduce2(s, sq);
        float m = s * (1.f / H), inv = rsqrtf(sq * (1.f / H) - m * m + EPS);
#pragma unroll
        for (int i = 0; i < 8; i++) {
            int c = lane + 32 * i;
            Ash[r * PA + c] = __float2half((v[i] - m) * inv * sg[c] + sbi[c]);
        }
    }
    __syncthreads();
    float acc[2][8][4];
#pragma unroll
    for (int mi = 0; mi < 2; mi++)
#pragma unroll
        for (int ni = 0; ni < 8; ni++)
            acc[mi][ni][0] = acc[mi][ni][1] = acc[mi][ni][2] = acc[mi][ni][3] = 0.f;
    mma_block(Ash, Wsh, acc, lane, wm, wn);
#pragma unroll
    for (int mi = 0; mi < 2; mi++) {
        int rb = g0 + 32 * wm + 16 * mi + (lane >> 2);
#pragma unroll
        for (int ni = 0; ni < 8; ni++) {
            int c = 64 * wn + 8 * ni + 2 * (lane & 3);
            float2 o0 = make_float2(gelu_f(acc[mi][ni][0] + sbias[c]),
                                    gelu_f(acc[mi][ni][1] + sbias[c + 1]));
            float2 o1 = make_float2(gelu_f(acc[mi][ni][2] + sbias[c]),
                                    gelu_f(acc[mi][ni][3] + sbias[c + 1]));
            *(float2 *)&g_film[(size_t)rb * H + c] = o0;
            *(float2 *)&g_film[(size_t)(rb + 8) * H + c] = o1;
        }
    }
}

// ---------------- pass1: fused 2-layer MLP, KCH=64, 2-buffer ring ----------------
__global__ __launch_bounds__(256, 2) void pass1_fused(
    const float *edge_tokens, const float *order_emb, const float *type_emb,
    const float *mlp_g, const float *mlp_b, const float *mlp_bias,
    const int *edge_batch, const int *sel_order, const void *mask) {
    __half *Ash = (__half *)dynsmem;                               // [64][PA]
    __half *Wb0 = (__half *)(dynsmem + MTE * PA * 2);              // [64][PW]
    __half *Wb1 = Wb0 + KCH * PW;
    __half *WbR[2] = {Wb0, Wb1};
    __shared__ float p_g0[H], p_b0[H], p_g1[H], p_b1[H], p_bias0[H], p_bias1[H], p_typ[H];
    __shared__ int sb[MTE], soi[MTE];
    __shared__ float smask[MTE], sS[MTE], sQ[MTE];

    int tid = threadIdx.x, lane = tid & 31, warp = tid >> 5;
    int wm = warp >> 2, wn = warp & 3;
    int mode = g_maskmode;
    int e0 = blockIdx.x * MTE;

    prefetch_chunk(WbR[0], hW0, 0, tid);   // P0, overlaps gather

    if (tid < H) {
        p_g0[tid] = mlp_g[tid]; p_b0[tid] = mlp_b[tid];
        p_g1[tid] = mlp_g[H + tid]; p_b1[tid] = mlp_b[H + tid];
        p_bias0[tid] = mlp_bias[tid]; p_bias1[tid] = mlp_bias[H + tid];
        p_typ[tid] = type_emb[2 * H + tid];
    }
    if (tid < MTE) {
        int e = e0 + tid;
        sb[tid] = edge_batch[e];
        int so = sel_order[e];
        so = so < -1 ? -1 : (so > 10 ? 10 : so);
        soi[tid] = so + 1;
        smask[tid] = mask_val(mask, e, mode);
        sS[tid] = 0.f; sQ[tid] = 0.f;
    }
    __syncthreads();

    // parallel cnt contribution
    if (tid < MTE) atomicAdd(&g_cnt[sb[tid]], smask[tid]);

    // gather + LN0 -> Ash: lane owns 8 contiguous columns, 2 rows in flight
    int cb = lane * 8;
    float tloc[8];
#pragma unroll
    for (int i = 0; i < 8; i++) tloc[i] = p_typ[cb + i];
#pragma unroll 1
    for (int it = 0; it < 4; it++) {
        int r0 = warp * 8 + 2 * it, r1 = r0 + 1;
        float v0[8], v1[8];
        {
            const float *et = edge_tokens + (size_t)(e0 + r0) * H + cb;
            const float *fl = g_film + (size_t)sb[r0] * H + cb;
            const float *oe = order_emb + (size_t)soi[r0] * H + cb;
            float4 ea = *(const float4 *)et, eb = *(const float4 *)(et + 4);
            float4 fa = *(const float4 *)fl, fb = *(const float4 *)(fl + 4);
            float4 oa = *(const float4 *)oe, ob = *(const float4 *)(oe + 4);
            v0[0] = ea.x + fa.x + oa.x + tloc[0];
            v0[1] = ea.y + fa.y + oa.y + tloc[1];
            v0[2] = ea.z + fa.z + oa.z + tloc[2];
            v0[3] = ea.w + fa.w + oa.w + tloc[3];
            v0[4] = eb.x + fb.x + ob.x + tloc[4];
            v0[5] = eb.y + fb.y + ob.y + tloc[5];
            v0[6] = eb.z + fb.z + ob.z + tloc[6];
            v0[7] = eb.w + fb.w + ob.w + tloc[7];
        }
        {
            const float *et = edge_tokens + (size_t)(e0 + r1) * H + cb;
            const float *fl = g_film + (size_t)sb[r1] * H + cb;
            const float *oe = order_emb + (size_t)soi[r1] * H + cb;
            float4 ea = *(const float4 *)et, eb = *(const float4 *)(et + 4);
            float4 fa = *(const float4 *)fl, fb = *(const float4 *)(fl + 4);
            float4 oa = *(const float4 *)oe, ob = *(const float4 *)(oe + 4);
            v1[0] = ea.x + fa.x + oa.x + tloc[0];
            v1[1] = ea.y + fa.y + oa.y + tloc[1];
            v1[2] = ea.z + fa.z + oa.z + tloc[2];
            v1[3] = ea.w + fa.w + oa.w + tloc[3];
            v1[4] = eb.x + fb.x + ob.x + tloc[4];
            v1[5] = eb.y + fb.y + ob.y + tloc[5];
            v1[6] = eb.z + fb.z + ob.z + tloc[6];
            v1[7] = eb.w + fb.w + ob.w + tloc[7];
        }
        float s0 = 0.f, q0 = 0.f, s1 = 0.f, q1 = 0.f;
#pragma unroll
        for (int i = 0; i < 8; i++) {
            s0 += v0[i]; q0 += v0[i] * v0[i];
            s1 += v1[i]; q1 += v1[i] * v1[i];
        }
        warpReduce2(s0, q0);
        warpReduce2(s1, q1);
        float m0 = s0 * (1.f / H), i0 = rsqrtf(q0 * (1.f / H) - m0 * m0 + EPS);
        float m1 = s1 * (1.f / H), i1 = rsqrtf(q1 * (1.f / H) - m1 * m1 + EPS);
        __half2 h0[4], h1[4];
#pragma unroll
        for (int j = 0; j < 4; j++) {
            int c = cb + 2 * j;
            h0[j] = __floats2half2_rn((v0[2 * j] - m0) * i0 * p_g0[c] + p_b0[c],
                                      (v0[2 * j + 1] - m0) * i0 * p_g0[c + 1] + p_b0[c + 1]);
            h1[j] = __floats2half2_rn((v1[2 * j] - m1) * i1 * p_g0[c] + p_b0[c],
                                      (v1[2 * j + 1] - m1) * i1 * p_g0[c + 1] + p_b0[c + 1]);
        }
        *(uint4 *)(Ash + r0 * PA + cb) = *(uint4 *)h0;
        *(uint4 *)(Ash + r1 * PA + cb) = *(uint4 *)h1;
    }

    // hoisted ldmatrix base addresses
    unsigned aB0 = s2u(Ash + (32 * wm + (lane & 15)) * PA + ((lane >> 4) << 3));
    unsigned aB1 = s2u(Ash + (32 * wm + 16 + (lane & 15)) * PA + ((lane >> 4) << 3));
    unsigned bB[2];
#pragma unroll
    for (int t = 0; t < 2; t++)
        bB[t] = s2u(WbR[t] + (lane & 15) * PW + 64 * wn + ((lane >> 4) << 3));

    float acc[2][8][4];
#pragma unroll
    for (int mi = 0; mi < 2; mi++)
#pragma unroll
        for (int ni = 0; ni < 8; ni++) {
            int c = 64 * wn + 8 * ni + 2 * (lane & 3);
            acc[mi][ni][0] = p_bias0[c];     acc[mi][ni][1] = p_bias0[c + 1];
            acc[mi][ni][2] = p_bias0[c];     acc[mi][ni][3] = p_bias0[c + 1];
        }
    // W0 chunk loop: 2-buffer, one sync per chunk
#pragma unroll 1
    for (int kc = 0; kc < NCH; kc++) {
        CP_WAIT0();
        __syncthreads();
        if (kc + 1 < NCH) prefetch_chunk(WbR[(kc + 1) & 1], hW0, kc + 1, tid);
        mma_chunk64(aB0, aB1, bB[kc & 1], acc, kc);
    }
    __syncthreads();
    prefetch_chunk(WbR[0], hW1, 0, tid);   // W1 P0

    // epilogue: gelu + LN1 stats
    float ps[2][2], pq[2][2];
#pragma unroll
    for (int mi = 0; mi < 2; mi++) { ps[mi][0] = ps[mi][1] = pq[mi][0] = pq[mi][1] = 0.f; }
#pragma unroll
    for (int mi = 0; mi < 2; mi++)
#pragma unroll
        for (int ni = 0; ni < 8; ni++)
#pragma unroll
            for (int hh = 0; hh < 2; hh++) {
                float v0 = gelu_f(acc[mi][ni][2 * hh]);
                float v1 = gelu_f(acc[mi][ni][2 * hh + 1]);
                acc[mi][ni][2 * hh] = v0; acc[mi][ni][2 * hh + 1] = v1;
                ps[mi][hh] += v0 + v1;
                pq[mi][hh] += v0 * v0 + v1 * v1;
            }
#pragma unroll
    for (int mi = 0; mi < 2; mi++)
#pragma unroll
        for (int hh = 0; hh < 2; hh++) {
            float s = quad_reduce(ps[mi][hh]);
            float q = quad_reduce(pq[mi][hh]);
            if ((lane & 3) == 0) {
                int r = 32 * wm + 16 * mi + 8 * hh + (lane >> 2);
                atomicAdd(&sS[r], s);
                atomicAdd(&sQ[r], q);
            }
        }
    __syncthreads();
    // normalize -> Ash (fp16), becomes A for layer 1
#pragma unroll
    for (int mi = 0; mi < 2; mi++)
#pragma unroll
        for (int hh = 0; hh < 2; hh++) {
            int r = 32 * wm + 16 * mi + 8 * hh + (lane >> 2);
            float m = sS[r] * (1.f / H);
            float inv = rsqrtf(sQ[r] * (1.f / H) - m * m + EPS);
#pragma unroll
            for (int ni = 0; ni < 8; ni++) {
                int c = 64 * wn + 8 * ni + 2 * (lane & 3);
                float n0 = (acc[mi][ni][2 * hh] - m) * inv * p_g1[c] + p_b1[c];
                float n1 = (acc[mi][ni][2 * hh + 1] - m) * inv * p_g1[c + 1] + p_b1[c + 1];
                *(__half2 *)&Ash[r * PA + c] = __floats2half2_rn(n0, n1);
            }
        }

#pragma unroll
    for (int mi = 0; mi < 2; mi++)
#pragma unroll
        for (int ni = 0; ni < 8; ni++) {
            int c = 64 * wn + 8 * ni + 2 * (lane & 3);
            acc[mi][ni][0] = p_bias1[c];     acc[mi][ni][1] = p_bias1[c + 1];
            acc[mi][ni][2] = p_bias1[c];     acc[mi][ni][3] = p_bias1[c + 1];
        }
    // W1 chunk loop
#pragma unroll 1
    for (int kc = 0; kc < NCH; kc++) {
        CP_WAIT0();
        __syncthreads();
        if (kc + 1 < NCH) prefetch_chunk(WbR[(kc + 1) & 1], hW1, kc + 1, tid);
        mma_chunk64(aB0, aB1, bB[kc & 1], acc, kc);
    }

    // x = gelu(acc) -> Ash (sync: all warps done reading Ash before overwrite)
    __syncthreads();
#pragma unroll
    for (int mi = 0; mi < 2; mi++)
#pragma unroll
        for (int hh = 0; hh < 2; hh++) {
            int r = 32 * wm + 16 * mi + 8 * hh + (lane >> 2);
#pragma unroll
            for (int ni = 0; ni < 8; ni++) {
                int c = 64 * wn + 8 * ni + 2 * (lane & 3);
                *(__half2 *)&Ash[r * PA + c] = __floats2half2_rn(
                    gelu_f(acc[mi][ni][2 * hh]), gelu_f(acc[mi][ni][2 * hh + 1]));
            }
        }
    __syncthreads();
    // write g_xh coalesced (2048 uint4)
#pragma unroll
    for (int it = 0; it < 8; it++) {
        int idx = tid + 256 * it;
        int row = idx >> 5, q = idx & 31;
        *(uint4 *)(g_xh + (size_t)(e0 + row) * H + q * 8) =
            *(const uint4 *)(Ash + row * PA + q * 8);
    }
    // masked scatter (sorted -> run-length); thread = column
    {
        float accs = 0.f;
        int bprev = sb[0];
        for (int r = 0; r < MTE; r++) {
            int b = sb[r];
            if (b != bprev) {
                atomicAdd(&g_selsum[bprev * H + tid], accs);
                accs = 0.f;
                bprev = b;
            }
            accs += smask[r] * __half2float(Ash[r * PA + tid]);
        }
        atomicAdd(&g_selsum[bprev * H + tid], accs);
    }
}

// ---------------- graphA: cur / stats / cg / zn ----------------
__global__ void graphA(const float *question, const float *gn_g,
                       const float *gn_b, const float *lh_g, const float *sp_g,
                       const float *sp_b, float *out_cur) {
    int g = blockIdx.x, j = threadIdx.x;
    float q = question[g * H + j];
    float cnt = g_cnt[g];
    float pre = g_selsum[g * H + j] / fmaxf(cnt, 1.f) + q;
    float s = pre, sq = pre * pre;
    blockReduce2(s, sq);
    float m = s * (1.f / H);
    float v = sq * (1.f / H) - m * m;
    float inv = rsqrtf(v + EPS);
    float cur = (pre - m) * inv * gn_g[j] + gn_b[j];
    out_cur[g * H + j] = cur;
    g_cg[g * H + j] = __float2half(cur * lh_g[j]);

    float cs = cur, csq = cur * cur;
    blockReduce2(cs, csq);
    if (j == 0) { g_cs[g] = cs; g_csq[g] = csq; }

    float qs = q, qsq = q * q;
    blockReduce2(qs, qsq);

    float m5 = (cs + qs) * (1.f / H2);
    float v5 = (csq + qsq) * (1.f / H2) - m5 * m5;
    float i5 = rsqrtf(v5 + EPS);
    g_zn[(size_t)g * H2 + j] = __float2half((cur - m5) * i5 * sp_g[j] + sp_b[j]);
    g_zn[(size_t)g * H2 + H + j] = __float2half((q - m5) * i5 * sp_g[H + j] + sp_b[H + j]);
}

// ---------------- pcstop: Pc (blocks 0..15) + stop head (blocks 16..31) ----------------
__global__ __launch_bounds__(NTH, 1) void pcstop_mma(const float *sp_b1,
                                                     const float *sp_W2,
                                                     const float *sp_b2,
                                                     float *out_stop) {
    __half *Wsh = (__half *)dynsmem;
    __half *Ash = (__half *)(dynsmem + WS_BYTES);
    int tid = threadIdx.x, lane = tid & 31, warp = tid >> 5;
    int wm = warp >> 2, wn = warp & 3;

    if (blockIdx.x < NT_G) {
        load_weights(Wsh, hPcW, tid);
        int g0 = blockIdx.x * MT;
#pragma unroll
        for (int it = 0; it < 8; it++) {
            int idx = tid + NTH * it;
            int row = idx >> 5, q = idx & 31;
            *(uint4 *)(Ash + row * PA + q * 8) =
                *(const uint4 *)(g_cg + (size_t)(g0 + row) * H + q * 8);
        }
        __syncthreads();
        float acc[2][8][4];
#pragma unroll
        for (int mi = 0; mi < 2; mi++)
#pragma unroll
            for (int ni = 0; ni < 8; ni++)
                acc[mi][ni][0] = acc[mi][ni][1] = acc[mi][ni][2] = acc[mi][ni][3] = 0.f;
        mma_block(Ash, Wsh, acc, lane, wm, wn);
#pragma unroll
        for (int mi = 0; mi < 2; mi++) {
            int rb = g0 + 32 * wm + 16 * mi + (lane >> 2);
#pragma unroll
            for (int ni = 0; ni < 8; ni++) {
                int c = 64 * wn + 8 * ni + 2 * (lane & 3);
                *(float2 *)&g_Pc[(size_t)rb * H + c] = make_float2(acc[mi][ni][0], acc[mi][ni][1]);
                *(float2 *)&g_Pc[(size_t)(rb + 8) * H + c] = make_float2(acc[mi][ni][2], acc[mi][ni][3]);
            }
        }
    } else {
        __shared__ float sb1[H], sw2[H], srow[MT];
        if (tid < H) { sb1[tid] = sp_b1[tid]; sw2[tid] = sp_W2[tid]; }
        if (tid < MT) srow[tid] = 0.f;
        int g0 = (blockIdx.x - NT_G) * MT;
        float acc[2][8][4];
#pragma unroll
        for (int mi = 0; mi < 2; mi++)
#pragma unroll
            for (int ni = 0; ni < 8; ni++)
                acc[mi][ni][0] = acc[mi][ni][1] = acc[mi][ni][2] = acc[mi][ni][3] = 0.f;
        for (int kc = 0; kc < 2; kc++) {
            __syncthreads();
            load_weights(Wsh, hSpW + kc * H * H, tid);
#pragma unroll
            for (int it = 0; it < 8; it++) {
                int idx = tid + NTH * it;
                int row = idx >> 5, q = idx & 31;
                *(uint4 *)(Ash + row * PA + q * 8) =
                    *(const uint4 *)(g_zn + (size_t)(g0 + row) * H2 + kc * H + q * 8);
            }
            __syncthreads();
            mma_block(Ash, Wsh, acc, lane, wm, wn);
        }
#pragma unroll
        for (int mi = 0; mi < 2; mi++)
#pragma unroll
            for (int hh = 0; hh < 2; hh++) {
                float sum = 0.f;
#pragma unroll
                for (int ni = 0; ni < 8; ni++) {
                    int c = 64 * wn + 8 * ni + 2 * (lane & 3);
                    sum += gelu_f(acc[mi][ni][2 * hh] + sb1[c]) * sw2[c];
                    sum += gelu_f(acc[mi][ni][2 * hh + 1] + sb1[c + 1]) * sw2[c + 1];
                }
                sum = quad_reduce(sum);
                if ((lane & 3) == 0) {
                    int r = 32 * wm + 16 * mi + 8 * hh + (lane >> 2);
                    atomicAdd(&srow[r], sum);
                }
            }
        __syncthreads();
        if (tid < MT) out_stop[g0 + tid] = srow[tid] + sp_b2[0];
    }
}

// ---------------- pass2: nxt LN -> @Wh (KCH=64, 2-buf) -> head epilogue ----------------
__global__ __launch_bounds__(256, 2) void pass2_str(const float *question,
                                                    const float *gn_g,
                                                    const float *gn_b,
                                                    const float *lh_W2,
                                                    const float *lh_b2,
                                                    const int *edge_batch,
                                                    float *out_edge) {
    __half *Ash = (__half *)dynsmem;
    __half *Wb0 = (__half *)(dynsmem + MTE * PA * 2);
    __half *Wb1 = Wb0 + KCH * PW;
    __half *WbR[2] = {Wb0, Wb1};
    __shared__ float sg[H], sbt[H], svg[H], svb[H], sw2n[H];
    __shared__ int sb[MTE];
    __shared__ float srm[MTE], sri[MTE], srow[MTE];
    int tid = threadIdx.x, lane = tid & 31, warp = tid >> 5;
    int wm = warp >> 2, wn = warp & 3;
    int e0 = blockIdx.x * MTE;

    prefetch_chunk(WbR[0], hWh, 0, tid);

    if (tid < H) {
        sg[tid] = gn_g[tid]; sbt[tid] = gn_b[tid];
        svg[tid] = g_vg[tid]; svb[tid] = g_vb[tid];
        sw2n[tid] = lh_W2[tid];
    }
    if (tid < MTE) {
        sb[tid] = edge_batch[e0 + tid];
        srow[tid] = 0.f;
    }
    float b2v = lh_b2[0];
    __syncthreads();

    // gather + LN -> Ash: lane owns 8 contiguous cols, 2 rows in flight
    int cb = lane * 8;
#pragma unroll 1
    for (int it = 0; it < 4; it++) {
        int r0 = warp * 8 + 2 * it, r1 = r0 + 1;
        float v0[8], v1[8];
        {
            int b = sb[r0];
            float invc = 1.f / (g_cnt[b] + 1.f);
            const float *ss = g_selsum + (size_t)b * H + cb;
            const __half *xh = g_xh + (size_t)(e0 + r0) * H + cb;
            const float *q = question + (size_t)b * H + cb;
            float4 sa = *(const float4 *)ss, sbv = *(const float4 *)(ss + 4);
            float4 qa = *(const float4 *)q, qb = *(const float4 *)(q + 4);
            uint4 hx = *(const uint4 *)xh;
            __half2 *hp = (__half2 *)&hx;
            float2 x0 = __half22float2(hp[0]), x1 = __half22float2(hp[1]);
            float2 x2 = __half22float2(hp[2]), x3 = __half22float2(hp[3]);
            v0[0] = (sa.x + x0.x) * invc + qa.x;
            v0[1] = (sa.y + x0.y) * invc + qa.y;
            v0[2] = (sa.z + x1.x) * invc + qa.z;
            v0[3] = (sa.w + x1.y) * invc + qa.w;
            v0[4] = (sbv.x + x2.x) * invc + qb.x;
            v0[5] = (sbv.y + x2.y) * invc + qb.y;
            v0[6] = (sbv.z + x3.x) * invc + qb.z;
            v0[7] = (sbv.w + x3.y) * invc + qb.w;
        }
        {
            int b = sb[r1];
            float invc = 1.f / (g_cnt[b] + 1.f);
            const float *ss = g_selsum + (size_t)b * H + cb;
            const __half *xh = g_xh + (size_t)(e0 + r1) * H + cb;
            const float *q = question + (size_t)b * H + cb;
            float4 sa = *(const float4 *)ss, sbv = *(const float4 *)(ss + 4);
            float4 qa = *(const float4 *)q, qb = *(const float4 *)(q + 4);
            uint4 hx = *(const uint4 *)xh;
            __half2 *hp = (__half2 *)&hx;
            float2 x0 = __half22float2(hp[0]), x1 = __half22float2(hp[1]);
            float2 x2 = __half22float2(hp[2]), x3 = __half22float2(hp[3]);
            v1[0] = (sa.x + x0.x) * invc + qa.x;
            v1[1] = (sa.y + x0.y) * invc + qa.y;
            v1[2] = (sa.z + x1.x) * invc + qa.z;
            v1[3] = (sa.w + x1.y) * invc + qa.w;
            v1[4] = (sbv.x + x2.x) * invc + qb.x;
            v1[5] = (sbv.y + x2.y) * invc + qb.y;
            v1[6] = (sbv.z + x3.x) * invc + qb.z;
            v1[7] = (sbv.w + x3.y) * invc + qb.w;
        }
        float s0 = 0.f, q0 = 0.f, s1 = 0.f, q1 = 0.f;
#pragma unroll
        for (int i = 0; i < 8; i++) {
            s0 += v0[i]; q0 += v0[i] * v0[i];
            s1 += v1[i]; q1 += v1[i] * v1[i];
        }
        warpReduce2(s0, q0);
        warpReduce2(s1, q1);
        float m0 = s0 * (1.f / H), i0 = rsqrtf(q0 * (1.f / H) - m0 * m0 + EPS);
        float m1 = s1 * (1.f / H), i1 = rsqrtf(q1 * (1.f / H) - m1 * m1 + EPS);
        float s20 = 0.f, sq20 = 0.f, s21 = 0.f, sq21 = 0.f;
        __half2 h0[4], h1[4];
#pragma unroll
        for (int j = 0; j < 4; j++) {
            int c = cb + 2 * j;
            float n00 = (v0[2 * j] - m0) * i0 * sg[c] + sbt[c];
            float n01 = (v0[2 * j + 1] - m0) * i0 * sg[c + 1] + sbt[c + 1];
            float n10 = (v1[2 * j] - m1) * i1 * sg[c] + sbt[c];
            float n11 = (v1[2 * j + 1] - m1) * i1 * sg[c + 1] + sbt[c + 1];
            s20 += n00 + n01; sq20 += n00 * n00 + n01 * n01;
            s21 += n10 + n11; sq21 += n10 * n10 + n11 * n11;
            h0[j] = __floats2half2_rn(n00, n01);
            h1[j] = __floats2half2_rn(n10, n11);
        }
        *(uint4 *)(Ash + r0 * PA + cb) = *(uint4 *)h0;
        *(uint4 *)(Ash + r1 * PA + cb) = *(uint4 *)h1;
        warpReduce2(s20, sq20);
        warpReduce2(s21, sq21);
        if (lane == 0) {
            int b0g = sb[r0], b1g = sb[r1];
            float M0 = (g_cs[b0g] + s20) * (1.f / H2);
            float V0 = (g_csq[b0g] + sq20) * (1.f / H2) - M0 * M0;
            srm[r0] = M0; sri[r0] = rsqrtf(V0 + EPS);
            float M1 = (g_cs[b1g] + s21) * (1.f / H2);
            float V1 = (g_csq[b1g] + sq21) * (1.f / H2) - M1 * M1;
            srm[r1] = M1; sri[r1] = rsqrtf(V1 + EPS);
        }
    }

    unsigned aB0 = s2u(Ash + (32 * wm + (lane & 15)) * PA + ((lane >> 4) << 3));
    unsigned aB1 = s2u(Ash + (32 * wm + 16 + (lane & 15)) * PA + ((lane >> 4) << 3));
    unsigned bB[2];
#pragma unroll
    for (int t = 0; t < 2; t++)
        bB[t] = s2u(WbR[t] + (lane & 15) * PW + 64 * wn + ((lane >> 4) << 3));

    float acc[2][8][4];
#pragma unroll
    for (int mi = 0; mi < 2; mi++)
#pragma unroll
        for (int ni = 0; ni < 8; ni++)
            acc[mi][ni][0] = acc[mi][ni][1] = acc[mi][ni][2] = acc[mi][ni][3] = 0.f;
#pragma unroll 1
    for (int kc = 0; kc < NCH; kc++) {
        CP_WAIT0();
        __syncthreads();
        if (kc + 1 < NCH) prefetch_chunk(WbR[(kc + 1) & 1], hWh, kc + 1, tid);
        mma_chunk64(aB0, aB1, bB[kc & 1], acc, kc);
    }

#pragma unroll
    for (int mi = 0; mi < 2; mi++)
#pragma unroll
        for (int hh = 0; hh < 2; hh++) {
            int r = 32 * wm + 16 * mi + 8 * hh + (lane >> 2);
            float rm = srm[r], ri = sri[r];
            int bg = sb[r];
            float sum = 0.f;
#pragma unroll
            for (int ni = 0; ni < 8; ni++) {
                int c = 64 * wn + 8 * ni + 2 * (lane & 3);
                float2 pc = *(const float2 *)&g_Pc[(size_t)bg * H + c];
                float h0 = (pc.x + acc[mi][ni][2 * hh] - rm * svg[c]) * ri + svb[c];
                float h1 = (pc.y + acc[mi][ni][2 * hh + 1] - rm * svg[c + 1]) * ri + svb[c + 1];
                sum += gelu_f(h0) * sw2n[c] + gelu_f(h1) * sw2n[c + 1];
            }
            sum = quad_reduce(sum);
            if ((lane & 3) == 0) atomicAdd(&srow[r], sum);
        }
    __syncthreads();
    if (tid < MTE) out_edge[e0 + tid] = srow[tid] + b2v;
}

// ---------------- launch ----------------
extern "C" void kernel_launch(void *const *d_in, const int *in_sizes, int n_in,
                              void *d_out, int out_size) {
    const float *edge_tokens = (const float *)d_in[0];
    const float *question = (const float *)d_in[1];
    const float *order_emb = (const float *)d_in[2];
    const float *type_emb = (const float *)d_in[3];
    const float *gn_g = (const float *)d_in[4];
    const float *gn_b = (const float *)d_in[5];
    const float *qf_g = (const float *)d_in[6];
    const float *qf_b = (const float *)d_in[7];
    const float *qf_W = (const float *)d_in[8];
    const float *qf_bias = (const float *)d_in[9];
    const float *mlp_g = (const float *)d_in[10];
    const float *mlp_b = (const float *)d_in[11];
    const float *mlp_W = (const float *)d_in[12];
    const float *mlp_bias = (const float *)d_in[13];
    const float *lh_g = (const float *)d_in[14];
    const float *lh_b = (const float *)d_in[15];
    const float *lh_W1 = (const float *)d_in[16];
    const float *lh_b1 = (const float *)d_in[17];
    const float *lh_W2 = (const float *)d_in[18];
    const float *lh_b2 = (const float *)d_in[19];
    const float *sp_g = (const float *)d_in[20];
    const float *sp_b = (const float *)d_in[21];
    const float *sp_W1 = (const float *)d_in[22];
    const float *sp_b1 = (const float *)d_in[23];
    const float *sp_W2 = (const float *)d_in[24];
    const float *sp_b2 = (const float *)d_in[25];
    const int *edge_batch = (const int *)d_in[26];
    const void *sel_mask = (const void *)d_in[27];
    const int *sel_order = (const int *)d_in[28];

    float *out_edge = (float *)d_out;
    float *out_stop = out_edge + E;
    float *out_cur = out_stop + G;

    cudaFuncSetAttribute(film_mma, cudaFuncAttributeMaxDynamicSharedMemorySize, DSMEM_G);
    cudaFuncSetAttribute(pcstop_mma, cudaFuncAttributeMaxDynamicSharedMemorySize, DSMEM_G);
    cudaFuncSetAttribute(pass1_fused, cudaFuncAttributeMaxDynamicSharedMemorySize, DSMEM_E);
    cudaFuncSetAttribute(pass2_str, cudaFuncAttributeMaxDynamicSharedMemorySize, DSMEM_E);

    prep_half2<<<7 * 256, 256>>>(qf_W, mlp_W, lh_g, lh_W1, sp_W1);
    film_mma<<<NT_G, NTH, DSMEM_G>>>(question, qf_g, qf_b, qf_bias);
    sniffzero_kernel<<<(G * H + 255) / 256, 256>>>(sel_mask);
    pass1_fused<<<E / MTE, 256, DSMEM_E>>>(edge_tokens, order_emb, type_emb,
                                           mlp_g, mlp_b, mlp_bias, edge_batch,
                                           sel_order, sel_mask);
    prep_vg<<<16, 256>>>(lh_g, lh_b, lh_W1, lh_b1);
    graphA<<<G, 256>>>(question, gn_g, gn_b, lh_g, sp_g, sp_b, out_cur);
    pcstop_mma<<<2 * NT_G, NTH, DSMEM_G>>>(sp_b1, sp_W2, sp_b2, out_stop);
    pass2_str<<<E / MTE, 256, DSMEM_E>>>(question, gn_g, gn_b, lh_W2, lh_b2,
                                         edge_batch, out_edge);
}

// round 17
// speedup vs baseline: 1.1311x; 1.0110x over previous
#include <cuda_runtime.h>
#include <cuda_fp16.h>
#include <stdint.h>
#include <math.h>

// Problem constants
#define H 256
#define H2 512
#define G 2048
#define E 262144
#define EPS 1e-5f
#define MT 128          // rows per tile (graph-side mma kernels)
#define MTE 64          // rows per tile (edge-side streamed kernels)
#define PA 264          // A-tile row stride (halves)
#define PW 264          // W-tile row stride (halves)
#define KCH 64          // K rows per streamed chunk
#define NCH 4           // chunks per 256-K matmul
#define NTH 512         // threads for graph-side mma kernels
#define NT_G (G / MT)   // 16 graph tiles

// ---------------- device scratch (16B aligned: vector access) ----------------
__device__ __align__(16) __half g_film[G * H];         // film output (fp16)
__device__ __align__(16) __half g_xh[(size_t)E * H];   // MLP out (x)
__device__ __align__(16) float  g_selsum[G * H];
__device__ __align__(16) float  g_cnt[G];
__device__ __align__(16) float  g_Pc[G * H];
__device__ __align__(16) float  g_cs[G], g_csq[G];
__device__ __align__(16) float  g_vg[H], g_vb[H];
__device__ __align__(16) __half g_cg[G * H];           // cur * lh_g_lo
__device__ __align__(16) __half g_zn[G * H2];          // stop-head LN512 out
__device__ __align__(16) __half hQf[H * H];
__device__ __align__(16) __half hW0[H * H];
__device__ __align__(16) __half hW1[H * H];
__device__ __align__(16) __half hWh[H * H];
__device__ __align__(16) __half hPcW[H * H];
__device__ __align__(16) __half hSpW[H2 * H];
__device__ int g_maskmode;

// ---------------- helpers ----------------
// Fast gelu: sigmoid form of tanh approximation.
__device__ __forceinline__ float gelu_f(float x) {
    float x2 = x * x;
    float u = 1.5957691216f * x * fmaf(0.044715f, x2, 1.0f);
    return __fdividef(x, 1.0f + __expf(-u));
}

__device__ __forceinline__ void warpReduce2(float &a, float &b) {
#pragma unroll
    for (int o = 16; o; o >>= 1) {
        a += __shfl_xor_sync(0xffffffffu, a, o);
        b += __shfl_xor_sync(0xffffffffu, b, o);
    }
}

// 256-thread block reduce (graphA only)
__device__ __forceinline__ void blockReduce2(float &a, float &b) {
    __shared__ float sa[8], sbx[8];
    int lane = threadIdx.x & 31, wid = threadIdx.x >> 5;
    warpReduce2(a, b);
    if (lane == 0) { sa[wid] = a; sbx[wid] = b; }
    __syncthreads();
    if (wid == 0) {
        a = (lane < 8) ? sa[lane] : 0.f;
        b = (lane < 8) ? sbx[lane] : 0.f;
#pragma unroll
        for (int o = 4; o; o >>= 1) {
            a += __shfl_xor_sync(0xffffffffu, a, o);
            b += __shfl_xor_sync(0xffffffffu, b, o);
        }
        if (lane == 0) { sa[0] = a; sbx[0] = b; }
    }
    __syncthreads();
    a = sa[0]; b = sbx[0];
    __syncthreads();
}

__device__ __forceinline__ float quad_reduce(float x) {
    x += __shfl_xor_sync(0xffffffffu, x, 1);
    x += __shfl_xor_sync(0xffffffffu, x, 2);
    return x;
}

__device__ __forceinline__ float mask_val(const void *p, int e, int mode) {
    if (mode == 0) return ((const int *)p)[e] != 0 ? 1.f : 0.f;
    if (mode == 1) return ((const float *)p)[e] != 0.f ? 1.f : 0.f;
    return ((const unsigned char *)p)[e] != 0 ? 1.f : 0.f;
}

__device__ __forceinline__ unsigned int s2u(const void *p) {
    return (unsigned int)__cvta_generic_to_shared(p);
}

__device__ __forceinline__ void ldm_x4(unsigned int &r0, unsigned int &r1,
                                       unsigned int &r2, unsigned int &r3,
                                       unsigned int addr) {
    asm volatile("ldmatrix.sync.aligned.m8n8.x4.shared.b16 {%0,%1,%2,%3}, [%4];"
                 : "=r"(r0), "=r"(r1), "=r"(r2), "=r"(r3) : "r"(addr));
}
__device__ __forceinline__ void ldm_x4_t(unsigned int &r0, unsigned int &r1,
                                         unsigned int &r2, unsigned int &r3,
                                         unsigned int addr) {
    asm volatile("ldmatrix.sync.aligned.m8n8.x4.trans.shared.b16 {%0,%1,%2,%3}, [%4];"
                 : "=r"(r0), "=r"(r1), "=r"(r2), "=r"(r3) : "r"(addr));
}
__device__ __forceinline__ void mma16816(float *c, unsigned int a0,
                                         unsigned int a1, unsigned int a2,
                                         unsigned int a3, unsigned int b0,
                                         unsigned int b1) {
    asm volatile(
        "mma.sync.aligned.m16n8k16.row.col.f32.f16.f16.f32 "
        "{%0,%1,%2,%3}, {%4,%5,%6,%7}, {%8,%9}, {%0,%1,%2,%3};"
        : "+f"(c[0]), "+f"(c[1]), "+f"(c[2]), "+f"(c[3])
        : "r"(a0), "r"(a1), "r"(a2), "r"(a3), "r"(b0), "r"(b1));
}

__device__ __forceinline__ void cp16(unsigned int saddr, const void *g) {
    asm volatile("cp.async.cg.shared.global [%0], [%1], 16;"
                 :: "r"(saddr), "l"(g) : "memory");
}
#define CP_COMMIT() asm volatile("cp.async.commit_group;" ::: "memory")
#define CP_WAIT0() asm volatile("cp.async.wait_group 0;" ::: "memory")

// ---- 16-warp graph-side mainloop: [128x256] @ [256x256], weights resident ----
__device__ __forceinline__ void mma_block(const __half *__restrict__ Ash,
                                          const __half *__restrict__ Wsh,
                                          float (&acc)[2][8][4], int lane,
                                          int wm, int wn) {
#pragma unroll 1
    for (int ks = 0; ks < 16; ks++) {
        unsigned int a[2][4];
#pragma unroll
        for (int mi = 0; mi < 2; mi++) {
            ldm_x4(a[mi][0], a[mi][1], a[mi][2], a[mi][3],
                   s2u(Ash + (32 * wm + 16 * mi + (lane & 15)) * PA + ks * 16 +
                       ((lane >> 4) << 3)));
        }
#pragma unroll
        for (int bi = 0; bi < 4; bi++) {
            unsigned int b0, b1, b2, b3;
            ldm_x4_t(b0, b1, b2, b3,
                     s2u(Wsh + (ks * 16 + (lane & 15)) * PW + 64 * wn + 16 * bi +
                         ((lane >> 4) << 3)));
#pragma unroll
            for (int mi = 0; mi < 2; mi++) {
                mma16816(acc[mi][2 * bi], a[mi][0], a[mi][1], a[mi][2], a[mi][3], b0, b1);
                mma16816(acc[mi][2 * bi + 1], a[mi][0], a[mi][1], a[mi][2], a[mi][3], b2, b3);
            }
        }
    }
}

// ---- edge-side chunk mainloop (KCH=64): 4 unrolled k-steps, hoisted bases ----
__device__ __forceinline__ void mma_chunk64(unsigned a0b, unsigned a1b,
                                            unsigned bb, float (&acc)[2][8][4],
                                            int kc) {
#pragma unroll
    for (int ks2 = 0; ks2 < 4; ks2++) {
        unsigned aoff = (unsigned)((kc * 4 + ks2) * 32);   // 16 halves = 32 B
        unsigned int a[2][4];
        ldm_x4(a[0][0], a[0][1], a[0][2], a[0][3], a0b + aoff);
        ldm_x4(a[1][0], a[1][1], a[1][2], a[1][3], a1b + aoff);
        unsigned bb2 = bb + (unsigned)(ks2 * (16 * PW * 2));
#pragma unroll
        for (int bi = 0; bi < 4; bi++) {
            unsigned int b0, b1, b2, b3;
            ldm_x4_t(b0, b1, b2, b3, bb2 + (unsigned)(bi * 32));
#pragma unroll
            for (int mi = 0; mi < 2; mi++) {
                mma16816(acc[mi][2 * bi], a[mi][0], a[mi][1], a[mi][2], a[mi][3], b0, b1);
                mma16816(acc[mi][2 * bi + 1], a[mi][0], a[mi][1], a[mi][2], a[mi][3], b2, b3);
            }
        }
    }
}

// prefetch one 64x256 weight chunk into smem via cp.async (2048 uint4, 256 thr)
__device__ __forceinline__ void prefetch_chunk(__half *Wc, const __half *Wg,
                                               int kc, int tid) {
    const __half *src = Wg + (size_t)kc * KCH * 256;
#pragma unroll
    for (int it = 0; it < 8; it++) {
        int idx = tid + 256 * it;       // 0..2047
        int row = idx >> 5, q = idx & 31;
        cp16(s2u(Wc + row * PW + q * 8), src + row * 256 + q * 8);
    }
    CP_COMMIT();
}

// load a 256x256 fp16 weight matrix into padded smem (8192 uint4, 512 threads)
__device__ __forceinline__ void load_weights(__half *Wsh, const __half *Wg, int tid) {
#pragma unroll
    for (int it = 0; it < 16; it++) {
        int idx = tid + NTH * it;
        int row = idx >> 5, q = idx & 31;
        *(uint4 *)(Wsh + row * PW + q * 8) = *(const uint4 *)(Wg + row * 256 + q * 8);
    }
}

extern __shared__ __align__(16) char dynsmem[];
#define WS_BYTES (256 * PW * 2)
#define DSMEM_G (WS_BYTES + MT * PA * 2)
#define DSMEM_E (MTE * PA * 2 + 2 * KCH * PW * 2)

// ---------------- K0: sniff + zero fused ----------------
__global__ void sniffzero_kernel(const void *mask) {
    if (blockIdx.x == 0) {
        const unsigned int *w = (const unsigned int *)mask;
        int i32ok = 1, f32ok = 1;
        for (int i = threadIdx.x; i < 4096; i += 256) {
            unsigned int x = w[i];
            if (x > 1u) i32ok = 0;
            float f = __uint_as_float(x);
            if (!(f == 0.f || f == 1.f)) f32ok = 0;
        }
        int all_i32 = __syncthreads_and(i32ok);
        int all_f32 = __syncthreads_and(f32ok);
        if (threadIdx.x == 0) g_maskmode = all_i32 ? 0 : (all_f32 ? 1 : 2);
    }
    int i = blockIdx.x * blockDim.x + threadIdx.x;
    if (i < G * H) g_selsum[i] = 0.f;
    if (i < G) g_cnt[i] = 0.f;
    if (i < H) { g_vg[i] = 0.f; g_vb[i] = 0.f; }
}

// ---------------- K2a: vg / vb (parallel atomic reduction, 16 blocks) ----------------
__global__ void prep_vg(const float *lh_g, const float *lh_b,
                        const float *lh_W1, const float *lh_b1) {
    int j = threadIdx.x;
    int k0 = blockIdx.x * 32;
    float a = 0.f, b = 0.f;
#pragma unroll
    for (int kk = 0; kk < 32; kk++) {
        int k = k0 + kk;
        float w = lh_W1[k * H + j];
        a += lh_g[k] * w;
        b += lh_b[k] * w;
    }
    atomicAdd(&g_vg[j], a);
    if (blockIdx.x == 0) b += lh_b1[j];
    atomicAdd(&g_vb[j], b);
}

// ---------------- K2b: fp16 weight conversion ----------------
__global__ void prep_half2(const float *qf_W, const float *mlp_W,
                           const float *lh_g, const float *lh_W1,
                           const float *sp_W1) {
    int i = blockIdx.x * 256 + threadIdx.x;
    int seg = i >> 16, off = i & 65535;
    switch (seg) {
        case 0: hQf[off] = __float2half(qf_W[off]); break;
        case 1: hW0[off] = __float2half(mlp_W[off]); break;
        case 2: hW1[off] = __float2half(mlp_W[65536 + off]); break;
        case 3: {
            int k = off >> 8;
            hWh[off] = __float2half(lh_g[H + k] * lh_W1[(H + k) * H + (off & 255)]);
        } break;
        case 4: hPcW[off] = __float2half(lh_W1[off]); break;
        case 5: hSpW[off] = __float2half(sp_W1[off]); break;
        case 6: hSpW[65536 + off] = __float2half(sp_W1[65536 + off]); break;
    }
}

// ---------------- film: g_film = gelu(LN(question)@qf_W + qf_bias), fp16 out ----------------
__global__ __launch_bounds__(NTH, 1) void film_mma(const float *question,
                                                   const float *qf_g,
                                                   const float *qf_b,
                                                   const float *qf_bias) {
    __half *Wsh = (__half *)dynsmem;
    __half *Ash = (__half *)(dynsmem + WS_BYTES);
    __shared__ float sg[H], sbi[H], sbias[H];
    int tid = threadIdx.x, lane = tid & 31, warp = tid >> 5;
    int wm = warp >> 2, wn = warp & 3;
    if (tid < H) { sg[tid] = qf_g[tid]; sbi[tid] = qf_b[tid]; sbias[tid] = qf_bias[tid]; }
    load_weights(Wsh, hQf, tid);
    __syncthreads();
    int g0 = blockIdx.x * MT;
    for (int rr = 0; rr < 8; rr++) {
        int r = warp * 8 + rr;
        const float *q = question + (size_t)(g0 + r) * H;
        float v[8], s = 0.f, sq = 0.f;
#pragma unroll
        for (int i = 0; i < 8; i++) {
            int c = lane + 32 * i;
            float x = q[c]; v[i] = x; s += x; sq += x * x;
        }
        warpReduce2(s, sq);
        float m = s * (1.f / H), inv = rsqrtf(sq * (1.f / H) - m * m + EPS);
#pragma unroll
        for (int i = 0; i < 8; i++) {
            int c = lane + 32 * i;
            Ash[r * PA + c] = __float2half((v[i] - m) * inv * sg[c] + sbi[c]);
        }
    }
    __syncthreads();
    float acc[2][8][4];
#pragma unroll
    for (int mi = 0; mi < 2; mi++)
#pragma unroll
        for (int ni = 0; ni < 8; ni++)
            acc[mi][ni][0] = acc[mi][ni][1] = acc[mi][ni][2] = acc[mi][ni][3] = 0.f;
    mma_block(Ash, Wsh, acc, lane, wm, wn);
#pragma unroll
    for (int mi = 0; mi < 2; mi++) {
        int rb = g0 + 32 * wm + 16 * mi + (lane >> 2);
#pragma unroll
        for (int ni = 0; ni < 8; ni++) {
            int c = 64 * wn + 8 * ni + 2 * (lane & 3);
            *(__half2 *)&g_film[(size_t)rb * H + c] =
                __floats2half2_rn(gelu_f(acc[mi][ni][0] + sbias[c]),
                                  gelu_f(acc[mi][ni][1] + sbias[c + 1]));
            *(__half2 *)&g_film[(size_t)(rb + 8) * H + c] =
                __floats2half2_rn(gelu_f(acc[mi][ni][2] + sbias[c]),
                                  gelu_f(acc[mi][ni][3] + sbias[c + 1]));
        }
    }
}

// ---------------- pass1: fused 2-layer MLP, KCH=64, 2-buffer ring ----------------
__global__ __launch_bounds__(256, 2) void pass1_fused(
    const float *edge_tokens, const float *order_emb, const float *type_emb,
    const float *mlp_g, const float *mlp_b, const float *mlp_bias,
    const int *edge_batch, const int *sel_order, const void *mask) {
    __half *Ash = (__half *)dynsmem;                               // [64][PA]
    __half *Wb0 = (__half *)(dynsmem + MTE * PA * 2);              // [64][PW]
    __half *Wb1 = Wb0 + KCH * PW;
    __half *WbR[2] = {Wb0, Wb1};
    __shared__ float p_g0[H], p_b0[H], p_g1[H], p_b1[H], p_bias0[H], p_bias1[H], p_typ[H];
    __shared__ int sb[MTE], soi[MTE];
    __shared__ float smask[MTE], sS[MTE], sQ[MTE];

    int tid = threadIdx.x, lane = tid & 31, warp = tid >> 5;
    int wm = warp >> 2, wn = warp & 3;
    int mode = g_maskmode;
    int e0 = blockIdx.x * MTE;

    prefetch_chunk(WbR[0], hW0, 0, tid);   // P0, overlaps gather

    if (tid < H) {
        p_g0[tid] = mlp_g[tid]; p_b0[tid] = mlp_b[tid];
        p_g1[tid] = mlp_g[H + tid]; p_b1[tid] = mlp_b[H + tid];
        p_bias0[tid] = mlp_bias[tid]; p_bias1[tid] = mlp_bias[H + tid];
        p_typ[tid] = type_emb[2 * H + tid];
    }
    if (tid < MTE) {
        int e = e0 + tid;
        sb[tid] = edge_batch[e];
        int so = sel_order[e];
        so = so < -1 ? -1 : (so > 10 ? 10 : so);
        soi[tid] = so + 1;
        smask[tid] = mask_val(mask, e, mode);
        sS[tid] = 0.f; sQ[tid] = 0.f;
    }
    __syncthreads();

    // parallel cnt contribution
    if (tid < MTE) atomicAdd(&g_cnt[sb[tid]], smask[tid]);

    // gather + LN0 -> Ash: lane owns 8 contiguous columns, 2 rows in flight,
    // unroll 2 (4 rows of loads in flight)
    int cb = lane * 8;
    float tloc[8];
#pragma unroll
    for (int i = 0; i < 8; i++) tloc[i] = p_typ[cb + i];
#pragma unroll 2
    for (int it = 0; it < 4; it++) {
        int r0 = warp * 8 + 2 * it, r1 = r0 + 1;
        float v0[8], v1[8];
        {
            const float *et = edge_tokens + (size_t)(e0 + r0) * H + cb;
            const __half *fl = g_film + (size_t)sb[r0] * H + cb;
            const float *oe = order_emb + (size_t)soi[r0] * H + cb;
            float4 ea = *(const float4 *)et, eb = *(const float4 *)(et + 4);
            uint4 fh = *(const uint4 *)fl;
            __half2 *fp = (__half2 *)&fh;
            float2 f0 = __half22float2(fp[0]), f1 = __half22float2(fp[1]);
            float2 f2 = __half22float2(fp[2]), f3 = __half22float2(fp[3]);
            float4 oa = *(const float4 *)oe, ob = *(const float4 *)(oe + 4);
            v0[0] = ea.x + f0.x + oa.x + tloc[0];
            v0[1] = ea.y + f0.y + oa.y + tloc[1];
            v0[2] = ea.z + f1.x + oa.z + tloc[2];
            v0[3] = ea.w + f1.y + oa.w + tloc[3];
            v0[4] = eb.x + f2.x + ob.x + tloc[4];
            v0[5] = eb.y + f2.y + ob.y + tloc[5];
            v0[6] = eb.z + f3.x + ob.z + tloc[6];
            v0[7] = eb.w + f3.y + ob.w + tloc[7];
        }
        {
            const float *et = edge_tokens + (size_t)(e0 + r1) * H + cb;
            const __half *fl = g_film + (size_t)sb[r1] * H + cb;
            const float *oe = order_emb + (size_t)soi[r1] * H + cb;
            float4 ea = *(const float4 *)et, eb = *(const float4 *)(et + 4);
            uint4 fh = *(const uint4 *)fl;
            __half2 *fp = (__half2 *)&fh;
            float2 f0 = __half22float2(fp[0]), f1 = __half22float2(fp[1]);
            float2 f2 = __half22float2(fp[2]), f3 = __half22float2(fp[3]);
            float4 oa = *(const float4 *)oe, ob = *(const float4 *)(oe + 4);
            v1[0] = ea.x + f0.x + oa.x + tloc[0];
            v1[1] = ea.y + f0.y + oa.y + tloc[1];
            v1[2] = ea.z + f1.x + oa.z + tloc[2];
            v1[3] = ea.w + f1.y + oa.w + tloc[3];
            v1[4] = eb.x + f2.x + ob.x + tloc[4];
            v1[5] = eb.y + f2.y + ob.y + tloc[5];
            v1[6] = eb.z + f3.x + ob.z + tloc[6];
            v1[7] = eb.w + f3.y + ob.w + tloc[7];
        }
        float s0 = 0.f, q0 = 0.f, s1 = 0.f, q1 = 0.f;
#pragma unroll
        for (int i = 0; i < 8; i++) {
            s0 += v0[i]; q0 += v0[i] * v0[i];
            s1 += v1[i]; q1 += v1[i] * v1[i];
        }
        warpReduce2(s0, q0);
        warpReduce2(s1, q1);
        float m0 = s0 * (1.f / H), i0 = rsqrtf(q0 * (1.f / H) - m0 * m0 + EPS);
        float m1 = s1 * (1.f / H), i1 = rsqrtf(q1 * (1.f / H) - m1 * m1 + EPS);
        __half2 h0[4], h1[4];
#pragma unroll
        for (int j = 0; j < 4; j++) {
            int c = cb + 2 * j;
            h0[j] = __floats2half2_rn((v0[2 * j] - m0) * i0 * p_g0[c] + p_b0[c],
                                      (v0[2 * j + 1] - m0) * i0 * p_g0[c + 1] + p_b0[c + 1]);
            h1[j] = __floats2half2_rn((v1[2 * j] - m1) * i1 * p_g0[c] + p_b0[c],
                                      (v1[2 * j + 1] - m1) * i1 * p_g0[c + 1] + p_b0[c + 1]);
        }
        *(uint4 *)(Ash + r0 * PA + cb) = *(uint4 *)h0;
        *(uint4 *)(Ash + r1 * PA + cb) = *(uint4 *)h1;
    }

    // hoisted ldmatrix base addresses
    unsigned aB0 = s2u(Ash + (32 * wm + (lane & 15)) * PA + ((lane >> 4) << 3));
    unsigned aB1 = s2u(Ash + (32 * wm + 16 + (lane & 15)) * PA + ((lane >> 4) << 3));
    unsigned bB[2];
#pragma unroll
    for (int t = 0; t < 2; t++)
        bB[t] = s2u(WbR[t] + (lane & 15) * PW + 64 * wn + ((lane >> 4) << 3));

    float acc[2][8][4];
#pragma unroll
    for (int mi = 0; mi < 2; mi++)
#pragma unroll
        for (int ni = 0; ni < 8; ni++) {
            int c = 64 * wn + 8 * ni + 2 * (lane & 3);
            acc[mi][ni][0] = p_bias0[c];     acc[mi][ni][1] = p_bias0[c + 1];
            acc[mi][ni][2] = p_bias0[c];     acc[mi][ni][3] = p_bias0[c + 1];
        }
    // W0 chunk loop: 2-buffer, one sync per chunk
#pragma unroll 1
    for (int kc = 0; kc < NCH; kc++) {
        CP_WAIT0();
        __syncthreads();
        if (kc + 1 < NCH) prefetch_chunk(WbR[(kc + 1) & 1], hW0, kc + 1, tid);
        mma_chunk64(aB0, aB1, bB[kc & 1], acc, kc);
    }
    __syncthreads();
    prefetch_chunk(WbR[0], hW1, 0, tid);   // W1 P0

    // epilogue: gelu + LN1 stats
    float ps[2][2], pq[2][2];
#pragma unroll
    for (int mi = 0; mi < 2; mi++) { ps[mi][0] = ps[mi][1] = pq[mi][0] = pq[mi][1] = 0.f; }
#pragma unroll
    for (int mi = 0; mi < 2; mi++)
#pragma unroll
        for (int ni = 0; ni < 8; ni++)
#pragma unroll
            for (int hh = 0; hh < 2; hh++) {
                float v0 = gelu_f(acc[mi][ni][2 * hh]);
                float v1 = gelu_f(acc[mi][ni][2 * hh + 1]);
                acc[mi][ni][2 * hh] = v0; acc[mi][ni][2 * hh + 1] = v1;
                ps[mi][hh] += v0 + v1;
                pq[mi][hh] += v0 * v0 + v1 * v1;
            }
#pragma unroll
    for (int mi = 0; mi < 2; mi++)
#pragma unroll
        for (int hh = 0; hh < 2; hh++) {
            float s = quad_reduce(ps[mi][hh]);
            float q = quad_reduce(pq[mi][hh]);
            if ((lane & 3) == 0) {
                int r = 32 * wm + 16 * mi + 8 * hh + (lane >> 2);
                atomicAdd(&sS[r], s);
                atomicAdd(&sQ[r], q);
            }
        }
    __syncthreads();
    // normalize -> Ash (fp16), becomes A for layer 1
#pragma unroll
    for (int mi = 0; mi < 2; mi++)
#pragma unroll
        for (int hh = 0; hh < 2; hh++) {
            int r = 32 * wm + 16 * mi + 8 * hh + (lane >> 2);
            float m = sS[r] * (1.f / H);
            float inv = rsqrtf(sQ[r] * (1.f / H) - m * m + EPS);
#pragma unroll
            for (int ni = 0; ni < 8; ni++) {
                int c = 64 * wn + 8 * ni + 2 * (lane & 3);
                float n0 = (acc[mi][ni][2 * hh] - m) * inv * p_g1[c] + p_b1[c];
                float n1 = (acc[mi][ni][2 * hh + 1] - m) * inv * p_g1[c + 1] + p_b1[c + 1];
                *(__half2 *)&Ash[r * PA + c] = __floats2half2_rn(n0, n1);
            }
        }

#pragma unroll
    for (int mi = 0; mi < 2; mi++)
#pragma unroll
        for (int ni = 0; ni < 8; ni++) {
            int c = 64 * wn + 8 * ni + 2 * (lane & 3);
            acc[mi][ni][0] = p_bias1[c];     acc[mi][ni][1] = p_bias1[c + 1];
            acc[mi][ni][2] = p_bias1[c];     acc[mi][ni][3] = p_bias1[c + 1];
        }
    // W1 chunk loop
#pragma unroll 1
    for (int kc = 0; kc < NCH; kc++) {
        CP_WAIT0();
        __syncthreads();
        if (kc + 1 < NCH) prefetch_chunk(WbR[(kc + 1) & 1], hW1, kc + 1, tid);
        mma_chunk64(aB0, aB1, bB[kc & 1], acc, kc);
    }

    // x = gelu(acc) -> Ash (sync: all warps done reading Ash before overwrite)
    __syncthreads();
#pragma unroll
    for (int mi = 0; mi < 2; mi++)
#pragma unroll
        for (int hh = 0; hh < 2; hh++) {
            int r = 32 * wm + 16 * mi + 8 * hh + (lane >> 2);
#pragma unroll
            for (int ni = 0; ni < 8; ni++) {
                int c = 64 * wn + 8 * ni + 2 * (lane & 3);
                *(__half2 *)&Ash[r * PA + c] = __floats2half2_rn(
                    gelu_f(acc[mi][ni][2 * hh]), gelu_f(acc[mi][ni][2 * hh + 1]));
            }
        }
    __syncthreads();
    // write g_xh coalesced (2048 uint4)
#pragma unroll
    for (int it = 0; it < 8; it++) {
        int idx = tid + 256 * it;
        int row = idx >> 5, q = idx & 31;
        *(uint4 *)(g_xh + (size_t)(e0 + row) * H + q * 8) =
            *(const uint4 *)(Ash + row * PA + q * 8);
    }
    // masked scatter (sorted -> run-length); thread = column
    {
        float accs = 0.f;
        int bprev = sb[0];
        for (int r = 0; r < MTE; r++) {
            int b = sb[r];
            if (b != bprev) {
                atomicAdd(&g_selsum[bprev * H + tid], accs);
                accs = 0.f;
                bprev = b;
            }
            accs += smask[r] * __half2float(Ash[r * PA + tid]);
        }
        atomicAdd(&g_selsum[bprev * H + tid], accs);
    }
}

// ---------------- graphA: cur / stats / cg / zn ----------------
__global__ void graphA(const float *question, const float *gn_g,
                       const float *gn_b, const float *lh_g, const float *sp_g,
                       const float *sp_b, float *out_cur) {
    int g = blockIdx.x, j = threadIdx.x;
    float q = question[g * H + j];
    float cnt = g_cnt[g];
    float pre = g_selsum[g * H + j] / fmaxf(cnt, 1.f) + q;
    float s = pre, sq = pre * pre;
    blockReduce2(s, sq);
    float m = s * (1.f / H);
    float v = sq * (1.f / H) - m * m;
    float inv = rsqrtf(v + EPS);
    float cur = (pre - m) * inv * gn_g[j] + gn_b[j];
    out_cur[g * H + j] = cur;
    g_cg[g * H + j] = __float2half(cur * lh_g[j]);

    float cs = cur, csq = cur * cur;
    blockReduce2(cs, csq);
    if (j == 0) { g_cs[g] = cs; g_csq[g] = csq; }

    float qs = q, qsq = q * q;
    blockReduce2(qs, qsq);

    float m5 = (cs + qs) * (1.f / H2);
    float v5 = (csq + qsq) * (1.f / H2) - m5 * m5;
    float i5 = rsqrtf(v5 + EPS);
    g_zn[(size_t)g * H2 + j] = __float2half((cur - m5) * i5 * sp_g[j] + sp_b[j]);
    g_zn[(size_t)g * H2 + H + j] = __float2half((q - m5) * i5 * sp_g[H + j] + sp_b[H + j]);
}

// ---------------- pcstop: Pc (blocks 0..15) + stop head (blocks 16..31) ----------------
__global__ __launch_bounds__(NTH, 1) void pcstop_mma(const float *sp_b1,
                                                     const float *sp_W2,
                                                     const float *sp_b2,
                                                     float *out_stop) {
    __half *Wsh = (__half *)dynsmem;
    __half *Ash = (__half *)(dynsmem + WS_BYTES);
    int tid = threadIdx.x, lane = tid & 31, warp = tid >> 5;
    int wm = warp >> 2, wn = warp & 3;

    if (blockIdx.x < NT_G) {
        load_weights(Wsh, hPcW, tid);
        int g0 = blockIdx.x * MT;
#pragma unroll
        for (int it = 0; it < 8; it++) {
            int idx = tid + NTH * it;
            int row = idx >> 5, q = idx & 31;
            *(uint4 *)(Ash + row * PA + q * 8) =
                *(const uint4 *)(g_cg + (size_t)(g0 + row) * H + q * 8);
        }
        __syncthreads();
        float acc[2][8][4];
#pragma unroll
        for (int mi = 0; mi < 2; mi++)
#pragma unroll
            for (int ni = 0; ni < 8; ni++)
                acc[mi][ni][0] = acc[mi][ni][1] = acc[mi][ni][2] = acc[mi][ni][3] = 0.f;
        mma_block(Ash, Wsh, acc, lane, wm, wn);
#pragma unroll
        for (int mi = 0; mi < 2; mi++) {
            int rb = g0 + 32 * wm + 16 * mi + (lane >> 2);
#pragma unroll
            for (int ni = 0; ni < 8; ni++) {
                int c = 64 * wn + 8 * ni + 2 * (lane & 3);
                *(float2 *)&g_Pc[(size_t)rb * H + c] = make_float2(acc[mi][ni][0], acc[mi][ni][1]);
                *(float2 *)&g_Pc[(size_t)(rb + 8) * H + c] = make_float2(acc[mi][ni][2], acc[mi][ni][3]);
            }
        }
    } else {
        __shared__ float sb1[H], sw2[H], srow[MT];
        if (tid < H) { sb1[tid] = sp_b1[tid]; sw2[tid] = sp_W2[tid]; }
        if (tid < MT) srow[tid] = 0.f;
        int g0 = (blockIdx.x - NT_G) * MT;
        float acc[2][8][4];
#pragma unroll
        for (int mi = 0; mi < 2; mi++)
#pragma unroll
            for (int ni = 0; ni < 8; ni++)
                acc[mi][ni][0] = acc[mi][ni][1] = acc[mi][ni][2] = acc[mi][ni][3] = 0.f;
        for (int kc = 0; kc < 2; kc++) {
            __syncthreads();
            load_weights(Wsh, hSpW + kc * H * H, tid);
#pragma unroll
            for (int it = 0; it < 8; it++) {
                int idx = tid + NTH * it;
                int row = idx >> 5, q = idx & 31;
                *(uint4 *)(Ash + row * PA + q * 8) =
                    *(const uint4 *)(g_zn + (size_t)(g0 + row) * H2 + kc * H + q * 8);
            }
            __syncthreads();
            mma_block(Ash, Wsh, acc, lane, wm, wn);
        }
#pragma unroll
        for (int mi = 0; mi < 2; mi++)
#pragma unroll
            for (int hh = 0; hh < 2; hh++) {
                float sum = 0.f;
#pragma unroll
                for (int ni = 0; ni < 8; ni++) {
                    int c = 64 * wn + 8 * ni + 2 * (lane & 3);
                    sum += gelu_f(acc[mi][ni][2 * hh] + sb1[c]) * sw2[c];
                    sum += gelu_f(acc[mi][ni][2 * hh + 1] + sb1[c + 1]) * sw2[c + 1];
                }
                sum = quad_reduce(sum);
                if ((lane & 3) == 0) {
                    int r = 32 * wm + 16 * mi + 8 * hh + (lane >> 2);
                    atomicAdd(&srow[r], sum);
                }
            }
        __syncthreads();
        if (tid < MT) out_stop[g0 + tid] = srow[tid] + sp_b2[0];
    }
}

// ---------------- pass2: nxt LN -> @Wh (KCH=64, 2-buf) -> head epilogue ----------------
__global__ __launch_bounds__(256, 2) void pass2_str(const float *question,
                                                    const float *gn_g,
                                                    const float *gn_b,
                                                    const float *lh_W2,
                                                    const float *lh_b2,
                                                    const int *edge_batch,
                                                    float *out_edge) {
    __half *Ash = (__half *)dynsmem;
    __half *Wb0 = (__half *)(dynsmem + MTE * PA * 2);
    __half *Wb1 = Wb0 + KCH * PW;
    __half *WbR[2] = {Wb0, Wb1};
    __shared__ float sg[H], sbt[H], svg[H], svb[H], sw2n[H];
    __shared__ int sb[MTE];
    __shared__ float srm[MTE], sri[MTE], srow[MTE];
    int tid = threadIdx.x, lane = tid & 31, warp = tid >> 5;
    int wm = warp >> 2, wn = warp & 3;
    int e0 = blockIdx.x * MTE;

    prefetch_chunk(WbR[0], hWh, 0, tid);

    if (tid < H) {
        sg[tid] = gn_g[tid]; sbt[tid] = gn_b[tid];
        svg[tid] = g_vg[tid]; svb[tid] = g_vb[tid];
        sw2n[tid] = lh_W2[tid];
    }
    if (tid < MTE) {
        sb[tid] = edge_batch[e0 + tid];
        srow[tid] = 0.f;
    }
    float b2v = lh_b2[0];
    __syncthreads();

    // gather + LN -> Ash: lane owns 8 contiguous cols, unroll 2
    int cb = lane * 8;
#pragma unroll 2
    for (int it = 0; it < 4; it++) {
        int r0 = warp * 8 + 2 * it, r1 = r0 + 1;
        float v0[8], v1[8];
        {
            int b = sb[r0];
            float invc = 1.f / (g_cnt[b] + 1.f);
            const float *ss = g_selsum + (size_t)b * H + cb;
            const __half *xh = g_xh + (size_t)(e0 + r0) * H + cb;
            const float *q = question + (size_t)b * H + cb;
            float4 sa = *(const float4 *)ss, sbv = *(const float4 *)(ss + 4);
            float4 qa = *(const float4 *)q, qb = *(const float4 *)(q + 4);
            uint4 hx = *(const uint4 *)xh;
            __half2 *hp = (__half2 *)&hx;
            float2 x0 = __half22float2(hp[0]), x1 = __half22float2(hp[1]);
            float2 x2 = __half22float2(hp[2]), x3 = __half22float2(hp[3]);
            v0[0] = (sa.x + x0.x) * invc + qa.x;
            v0[1] = (sa.y + x0.y) * invc + qa.y;
            v0[2] = (sa.z + x1.x) * invc + qa.z;
            v0[3] = (sa.w + x1.y) * invc + qa.w;
            v0[4] = (sbv.x + x2.x) * invc + qb.x;
            v0[5] = (sbv.y + x2.y) * invc + qb.y;
            v0[6] = (sbv.z + x3.x) * invc + qb.z;
            v0[7] = (sbv.w + x3.y) * invc + qb.w;
        }
        {
            int b = sb[r1];
            float invc = 1.f / (g_cnt[b] + 1.f);
            const float *ss = g_selsum + (size_t)b * H + cb;
            const __half *xh = g_xh + (size_t)(e0 + r1) * H + cb;
            const float *q = question + (size_t)b * H + cb;
            float4 sa = *(const float4 *)ss, sbv = *(const float4 *)(ss + 4);
            float4 qa = *(const float4 *)q, qb = *(const float4 *)(q + 4);
            uint4 hx = *(const uint4 *)xh;
            __half2 *hp = (__half2 *)&hx;
            float2 x0 = __half22float2(hp[0]), x1 = __half22float2(hp[1]);
            float2 x2 = __half22float2(hp[2]), x3 = __half22float2(hp[3]);
            v1[0] = (sa.x + x0.x) * invc + qa.x;
            v1[1] = (sa.y + x0.y) * invc + qa.y;
            v1[2] = (sa.z + x1.x) * invc + qa.z;
            v1[3] = (sa.w + x1.y) * invc + qa.w;
            v1[4] = (sbv.x + x2.x) * invc + qb.x;
            v1[5] = (sbv.y + x2.y) * invc + qb.y;
            v1[6] = (sbv.z + x3.x) * invc + qb.z;
            v1[7] = (sbv.w + x3.y) * invc + qb.w;
        }
        float s0 = 0.f, q0 = 0.f, s1 = 0.f, q1 = 0.f;
#pragma unroll
        for (int i = 0; i < 8; i++) {
            s0 += v0[i]; q0 += v0[i] * v0[i];
            s1 += v1[i]; q1 += v1[i] * v1[i];
        }
        warpReduce2(s0, q0);
        warpReduce2(s1, q1);
        float m0 = s0 * (1.f / H), i0 = rsqrtf(q0 * (1.f / H) - m0 * m0 + EPS);
        float m1 = s1 * (1.f / H), i1 = rsqrtf(q1 * (1.f / H) - m1 * m1 + EPS);
        float s20 = 0.f, sq20 = 0.f, s21 = 0.f, sq21 = 0.f;
        __half2 h0[4], h1[4];
#pragma unroll
        for (int j = 0; j < 4; j++) {
            int c = cb + 2 * j;
            float n00 = (v0[2 * j] - m0) * i0 * sg[c] + sbt[c];
            float n01 = (v0[2 * j + 1] - m0) * i0 * sg[c + 1] + sbt[c + 1];
            float n10 = (v1[2 * j] - m1) * i1 * sg[c] + sbt[c];
            float n11 = (v1[2 * j + 1] - m1) * i1 * sg[c + 1] + sbt[c + 1];
            s20 += n00 + n01; sq20 += n00 * n00 + n01 * n01;
            s21 += n10 + n11; sq21 += n10 * n10 + n11 * n11;
            h0[j] = __floats2half2_rn(n00, n01);
            h1[j] = __floats2half2_rn(n10, n11);
        }
        *(uint4 *)(Ash + r0 * PA + cb) = *(uint4 *)h0;
        *(uint4 *)(Ash + r1 * PA + cb) = *(uint4 *)h1;
        warpReduce2(s20, sq20);
        warpReduce2(s21, sq21);
        if (lane == 0) {
            int b0g = sb[r0], b1g = sb[r1];
            float M0 = (g_cs[b0g] + s20) * (1.f / H2);
            float V0 = (g_csq[b0g] + sq20) * (1.f / H2) - M0 * M0;
            srm[r0] = M0; sri[r0] = rsqrtf(V0 + EPS);
            float M1 = (g_cs[b1g] + s21) * (1.f / H2);
            float V1 = (g_csq[b1g] + sq21) * (1.f / H2) - M1 * M1;
            srm[r1] = M1; sri[r1] = rsqrtf(V1 + EPS);
        }
    }

    unsigned aB0 = s2u(Ash + (32 * wm + (lane & 15)) * PA + ((lane >> 4) << 3));
    unsigned aB1 = s2u(Ash + (32 * wm + 16 + (lane & 15)) * PA + ((lane >> 4) << 3));
    unsigned bB[2];
#pragma unroll
    for (int t = 0; t < 2; t++)
        bB[t] = s2u(WbR[t] + (lane & 15) * PW + 64 * wn + ((lane >> 4) << 3));

    float acc[2][8][4];
#pragma unroll
    for (int mi = 0; mi < 2; mi++)
#pragma unroll
        for (int ni = 0; ni < 8; ni++)
            acc[mi][ni][0] = acc[mi][ni][1] = acc[mi][ni][2] = acc[mi][ni][3] = 0.f;
#pragma unroll 1
    for (int kc = 0; kc < NCH; kc++) {
        CP_WAIT0();
        __syncthreads();
        if (kc + 1 < NCH) prefetch_chunk(WbR[(kc + 1) & 1], hWh, kc + 1, tid);
        mma_chunk64(aB0, aB1, bB[kc & 1], acc, kc);
    }

#pragma unroll
    for (int mi = 0; mi < 2; mi++)
#pragma unroll
        for (int hh = 0; hh < 2; hh++) {
            int r = 32 * wm + 16 * mi + 8 * hh + (lane >> 2);
            float rm = srm[r], ri = sri[r];
            int bg = sb[r];
            float sum = 0.f;
#pragma unroll
            for (int ni = 0; ni < 8; ni++) {
                int c = 64 * wn + 8 * ni + 2 * (lane & 3);
                float2 pc = *(const float2 *)&g_Pc[(size_t)bg * H + c];
                float h0 = (pc.x + acc[mi][ni][2 * hh] - rm * svg[c]) * ri + svb[c];
                float h1 = (pc.y + acc[mi][ni][2 * hh + 1] - rm * svg[c + 1]) * ri + svb[c + 1];
                sum += gelu_f(h0) * sw2n[c] + gelu_f(h1) * sw2n[c + 1];
            }
            sum = quad_reduce(sum);
            if ((lane & 3) == 0) atomicAdd(&srow[r], sum);
        }
    __syncthreads();
    if (tid < MTE) out_edge[e0 + tid] = srow[tid] + b2v;
}

// ---------------- launch ----------------
extern "C" void kernel_launch(void *const *d_in, const int *in_sizes, int n_in,
                              void *d_out, int out_size) {
    const float *edge_tokens = (const float *)d_in[0];
    const float *question = (const float *)d_in[1];
    const float *order_emb = (const float *)d_in[2];
    const float *type_emb = (const float *)d_in[3];
    const float *gn_g = (const float *)d_in[4];
    const float *gn_b = (const float *)d_in[5];
    const float *qf_g = (const float *)d_in[6];
    const float *qf_b = (const float *)d_in[7];
    const float *qf_W = (const float *)d_in[8];
    const float *qf_bias = (const float *)d_in[9];
    const float *mlp_g = (const float *)d_in[10];
    const float *mlp_b = (const float *)d_in[11];
    const float *mlp_W = (const float *)d_in[12];
    const float *mlp_bias = (const float *)d_in[13];
    const float *lh_g = (const float *)d_in[14];
    const float *lh_b = (const float *)d_in[15];
    const float *lh_W1 = (const float *)d_in[16];
    const float *lh_b1 = (const float *)d_in[17];
    const float *lh_W2 = (const float *)d_in[18];
    const float *lh_b2 = (const float *)d_in[19];
    const float *sp_g = (const float *)d_in[20];
    const float *sp_b = (const float *)d_in[21];
    const float *sp_W1 = (const float *)d_in[22];
    const float *sp_b1 = (const float *)d_in[23];
    const float *sp_W2 = (const float *)d_in[24];
    const float *sp_b2 = (const float *)d_in[25];
    const int *edge_batch = (const int *)d_in[26];
    const void *sel_mask = (const void *)d_in[27];
    const int *sel_order = (const int *)d_in[28];

    float *out_edge = (float *)d_out;
    float *out_stop = out_edge + E;
    float *out_cur = out_stop + G;

    cudaFuncSetAttribute(film_mma, cudaFuncAttributeMaxDynamicSharedMemorySize, DSMEM_G);
    cudaFuncSetAttribute(pcstop_mma, cudaFuncAttributeMaxDynamicSharedMemorySize, DSMEM_G);
    cudaFuncSetAttribute(pass1_fused, cudaFuncAttributeMaxDynamicSharedMemorySize, DSMEM_E);
    cudaFuncSetAttribute(pass2_str, cudaFuncAttributeMaxDynamicSharedMemorySize, DSMEM_E);

    prep_half2<<<7 * 256, 256>>>(qf_W, mlp_W, lh_g, lh_W1, sp_W1);
    film_mma<<<NT_G, NTH, DSMEM_G>>>(question, qf_g, qf_b, qf_bias);
    sniffzero_kernel<<<(G * H + 255) / 256, 256>>>(sel_mask);
    pass1_fused<<<E / MTE, 256, DSMEM_E>>>(edge_tokens, order_emb, type_emb,
                                           mlp_g, mlp_b, mlp_bias, edge_batch,
                                           sel_order, sel_mask);
    prep_vg<<<16, 256>>>(lh_g, lh_b, lh_W1, lh_b1);
    graphA<<<G, 256>>>(question, gn_g, gn_b, lh_g, sp_g, sp_b, out_cur);
    pcstop_mma<<<2 * NT_G, NTH, DSMEM_G>>>(sp_b1, sp_W2, sp_b2, out_stop);
    pass2_str<<<E / MTE, 256, DSMEM_E>>>(question, gn_g, gn_b, lh_W2, lh_b2,
                                         edge_batch, out_edge);
}